// round 1
// baseline (speedup 1.0000x reference)
#include <cuda_runtime.h>

#define NB 8
#define LSEQ 2048
#define DIM 128

// 8 * 2048 * 2048 floats = 128 MiB scratch for the attention matrix S / P.
static __device__ float g_S[(size_t)NB * LSEQ * LSEQ];

// ---------------------------------------------------------------------------
// GEMM1: S[b,c,m] = sum_d context[b,c,d] * main[b,m,d]
// 128x128 CTA tile, BK=16, 256 threads, 8x8 micro-tile.
// Both operands are K-major (d contiguous) -> transpose on the smem store.
// ---------------------------------------------------------------------------
__global__ __launch_bounds__(256, 2) void gemm1_kernel(const float* __restrict__ ctx,
                                                       const float* __restrict__ mn) {
    __shared__ float As[16][128];  // [k][c]
    __shared__ float Bs[16][128];  // [k][m]

    const int b  = blockIdx.z;
    const int c0 = blockIdx.y * 128;
    const int m0 = blockIdx.x * 128;

    const float* A  = ctx + (size_t)b * LSEQ * DIM;
    const float* Bm = mn  + (size_t)b * LSEQ * DIM;
    float*       S  = g_S + (size_t)b * LSEQ * LSEQ;

    const int tid = threadIdx.x;
    const int lr  = tid >> 1;        // 0..127 (tile row)
    const int lk  = (tid & 1) * 8;   // 0 or 8 (k offset)
    const int ty  = tid >> 4;        // 0..15
    const int tx  = tid & 15;        // 0..15

    float acc[8][8];
#pragma unroll
    for (int i = 0; i < 8; i++)
#pragma unroll
        for (int j = 0; j < 8; j++) acc[i][j] = 0.0f;

    for (int k0 = 0; k0 < DIM; k0 += 16) {
        float4 a0 = *(const float4*)&A [(size_t)(c0 + lr) * DIM + k0 + lk];
        float4 a1 = *(const float4*)&A [(size_t)(c0 + lr) * DIM + k0 + lk + 4];
        float4 b0 = *(const float4*)&Bm[(size_t)(m0 + lr) * DIM + k0 + lk];
        float4 b1 = *(const float4*)&Bm[(size_t)(m0 + lr) * DIM + k0 + lk + 4];

        __syncthreads();  // previous iteration's consumers done before overwrite
        As[lk + 0][lr] = a0.x; As[lk + 1][lr] = a0.y;
        As[lk + 2][lr] = a0.z; As[lk + 3][lr] = a0.w;
        As[lk + 4][lr] = a1.x; As[lk + 5][lr] = a1.y;
        As[lk + 6][lr] = a1.z; As[lk + 7][lr] = a1.w;
        Bs[lk + 0][lr] = b0.x; Bs[lk + 1][lr] = b0.y;
        Bs[lk + 2][lr] = b0.z; Bs[lk + 3][lr] = b0.w;
        Bs[lk + 4][lr] = b1.x; Bs[lk + 5][lr] = b1.y;
        Bs[lk + 6][lr] = b1.z; Bs[lk + 7][lr] = b1.w;
        __syncthreads();

#pragma unroll
        for (int k = 0; k < 16; k++) {
            float a[8], bb[8];
            *(float4*)&a [0] = *(const float4*)&As[k][ty * 8];
            *(float4*)&a [4] = *(const float4*)&As[k][ty * 8 + 4];
            *(float4*)&bb[0] = *(const float4*)&Bs[k][tx * 8];
            *(float4*)&bb[4] = *(const float4*)&Bs[k][tx * 8 + 4];
#pragma unroll
            for (int i = 0; i < 8; i++)
#pragma unroll
                for (int j = 0; j < 8; j++) acc[i][j] += a[i] * bb[j];
        }
    }

#pragma unroll
    for (int i = 0; i < 8; i++) {
        float* p = &S[(size_t)(c0 + ty * 8 + i) * LSEQ + m0 + tx * 8];
        *(float4*)(p + 0) = make_float4(acc[i][0], acc[i][1], acc[i][2], acc[i][3]);
        *(float4*)(p + 4) = make_float4(acc[i][4], acc[i][5], acc[i][6], acc[i][7]);
    }
}

// ---------------------------------------------------------------------------
// Row softmax over m (row length 2048). One 256-thread block per (b,c) row.
// ---------------------------------------------------------------------------
__global__ __launch_bounds__(256) void softmax_kernel() {
    float* S = g_S + (size_t)blockIdx.x * LSEQ;
    float4* S4 = (float4*)S;
    const int tid = threadIdx.x;

    float4 x0 = S4[tid];
    float4 x1 = S4[tid + 256];

    float mx = fmaxf(fmaxf(fmaxf(x0.x, x0.y), fmaxf(x0.z, x0.w)),
                     fmaxf(fmaxf(x1.x, x1.y), fmaxf(x1.z, x1.w)));
#pragma unroll
    for (int o = 16; o > 0; o >>= 1) mx = fmaxf(mx, __shfl_xor_sync(0xffffffffu, mx, o));

    __shared__ float red[8];
    if ((tid & 31) == 0) red[tid >> 5] = mx;
    __syncthreads();
    mx = red[0];
#pragma unroll
    for (int w = 1; w < 8; w++) mx = fmaxf(mx, red[w]);

    x0.x = __expf(x0.x - mx); x0.y = __expf(x0.y - mx);
    x0.z = __expf(x0.z - mx); x0.w = __expf(x0.w - mx);
    x1.x = __expf(x1.x - mx); x1.y = __expf(x1.y - mx);
    x1.z = __expf(x1.z - mx); x1.w = __expf(x1.w - mx);

    float s = (x0.x + x0.y + x0.z + x0.w) + (x1.x + x1.y + x1.z + x1.w);
#pragma unroll
    for (int o = 16; o > 0; o >>= 1) s += __shfl_xor_sync(0xffffffffu, s, o);

    __syncthreads();  // red reuse
    if ((tid & 31) == 0) red[tid >> 5] = s;
    __syncthreads();
    s = red[0];
#pragma unroll
    for (int w = 1; w < 8; w++) s += red[w];

    const float inv = 1.0f / s;
    x0.x *= inv; x0.y *= inv; x0.z *= inv; x0.w *= inv;
    x1.x *= inv; x1.y *= inv; x1.z *= inv; x1.w *= inv;
    S4[tid] = x0;
    S4[tid + 256] = x1;
}

// ---------------------------------------------------------------------------
// GEMM2: out[b,m,d] = main[b,m,d] - sum_c P[b,c,m] * context[b,c,d]
// M=2048 (m), N=128 (d, one tile), K=2048 (c). 128x128 tile, BK=16.
// Both smem tiles load contiguous rows -> direct float4 stores, no transpose.
// ---------------------------------------------------------------------------
__global__ __launch_bounds__(256, 2) void gemm2_kernel(const float* __restrict__ ctx,
                                                       const float* __restrict__ mn,
                                                       float* __restrict__ out) {
    __shared__ float Ps[16][128];  // [kc][m]
    __shared__ float Cs[16][128];  // [kc][d]

    const int b  = blockIdx.z;
    const int m0 = blockIdx.y * 128;

    const float* P = g_S + (size_t)b * LSEQ * LSEQ;
    const float* C = ctx + (size_t)b * LSEQ * DIM;
    const float* M = mn  + (size_t)b * LSEQ * DIM;
    float*       O = out + (size_t)b * LSEQ * DIM;

    const int tid = threadIdx.x;
    const int kc  = tid >> 4;        // 0..15
    const int q8  = (tid & 15) * 8;  // 0..120
    const int ty  = tid >> 4;
    const int tx  = tid & 15;

    float acc[8][8];
#pragma unroll
    for (int i = 0; i < 8; i++)
#pragma unroll
        for (int j = 0; j < 8; j++) acc[i][j] = 0.0f;

    for (int c0 = 0; c0 < LSEQ; c0 += 16) {
        float4 p0 = *(const float4*)&P[(size_t)(c0 + kc) * LSEQ + m0 + q8];
        float4 p1 = *(const float4*)&P[(size_t)(c0 + kc) * LSEQ + m0 + q8 + 4];
        float4 c0v = *(const float4*)&C[(size_t)(c0 + kc) * DIM + q8];
        float4 c1v = *(const float4*)&C[(size_t)(c0 + kc) * DIM + q8 + 4];

        __syncthreads();
        *(float4*)&Ps[kc][q8]     = p0;
        *(float4*)&Ps[kc][q8 + 4] = p1;
        *(float4*)&Cs[kc][q8]     = c0v;
        *(float4*)&Cs[kc][q8 + 4] = c1v;
        __syncthreads();

#pragma unroll
        for (int k = 0; k < 16; k++) {
            float a[8], bb[8];
            *(float4*)&a [0] = *(const float4*)&Ps[k][ty * 8];
            *(float4*)&a [4] = *(const float4*)&Ps[k][ty * 8 + 4];
            *(float4*)&bb[0] = *(const float4*)&Cs[k][tx * 8];
            *(float4*)&bb[4] = *(const float4*)&Cs[k][tx * 8 + 4];
#pragma unroll
            for (int i = 0; i < 8; i++)
#pragma unroll
                for (int j = 0; j < 8; j++) acc[i][j] += a[i] * bb[j];
        }
    }

#pragma unroll
    for (int i = 0; i < 8; i++) {
        const size_t off = (size_t)(m0 + ty * 8 + i) * DIM + tx * 8;
        float4 mv0 = *(const float4*)&M[off];
        float4 mv1 = *(const float4*)&M[off + 4];
        *(float4*)&O[off] = make_float4(mv0.x - acc[i][0], mv0.y - acc[i][1],
                                        mv0.z - acc[i][2], mv0.w - acc[i][3]);
        *(float4*)&O[off + 4] = make_float4(mv1.x - acc[i][4], mv1.y - acc[i][5],
                                            mv1.z - acc[i][6], mv1.w - acc[i][7]);
    }
}

extern "C" void kernel_launch(void* const* d_in, const int* in_sizes, int n_in,
                              void* d_out, int out_size) {
    (void)in_sizes; (void)n_in; (void)out_size;
    const float* ctx = (const float*)d_in[0];  // context: (8, 2048, 128) f32
    const float* mn  = (const float*)d_in[1];  // main:    (8, 2048, 128) f32
    float* out = (float*)d_out;                // (8, 2048, 128) f32

    dim3 g1(LSEQ / 128, LSEQ / 128, NB);       // 16 x 16 x 8
    gemm1_kernel<<<g1, 256>>>(ctx, mn);

    softmax_kernel<<<NB * LSEQ, 256>>>();

    dim3 g2(1, LSEQ / 128, NB);                // 1 x 16 x 8
    gemm2_kernel<<<g2, 256>>>(ctx, mn, out);
}

// round 2
// speedup vs baseline: 1.1723x; 1.1723x over previous
#include <cuda_runtime.h>

#define NB 8
#define LSEQ 2048
#define DIM 128
#define NSPLIT 8
#define KSPLIT (LSEQ / NSPLIT)   // 256

// 128 MiB scratch for the attention matrix S / P.
static __device__ float g_S[(size_t)NB * LSEQ * LSEQ];
// 64 MiB scratch for split-K partials of GEMM2: [split][b][m][d]
static __device__ float g_part[(size_t)NSPLIT * NB * LSEQ * DIM];

// ---------------------------------------------------------------------------
// GEMM1: S[b,c,m] = sum_d context[b,c,d] * main[b,m,d]
// 128x128 CTA tile, BK=16, 256 threads, 8x8 micro-tile, double-buffered smem.
// ---------------------------------------------------------------------------
__global__ __launch_bounds__(256, 2) void gemm1_kernel(const float* __restrict__ ctx,
                                                       const float* __restrict__ mn) {
    __shared__ float As[2][16][128];  // [stage][k][c]
    __shared__ float Bs[2][16][128];  // [stage][k][m]

    const int b  = blockIdx.z;
    const int c0 = blockIdx.y * 128;
    const int m0 = blockIdx.x * 128;

    const float* A  = ctx + (size_t)b * LSEQ * DIM;
    const float* Bm = mn  + (size_t)b * LSEQ * DIM;
    float*       S  = g_S + (size_t)b * LSEQ * LSEQ;

    const int tid = threadIdx.x;
    const int lr  = tid >> 1;        // 0..127 (tile row)
    const int lk  = (tid & 1) * 8;   // 0 or 8 (k offset)
    const int ty  = tid >> 4;        // 0..15
    const int tx  = tid & 15;        // 0..15

    float acc[8][8];
#pragma unroll
    for (int i = 0; i < 8; i++)
#pragma unroll
        for (int j = 0; j < 8; j++) acc[i][j] = 0.0f;

    // prologue: stage 0
    {
        float4 a0 = *(const float4*)&A [(size_t)(c0 + lr) * DIM + lk];
        float4 a1 = *(const float4*)&A [(size_t)(c0 + lr) * DIM + lk + 4];
        float4 b0 = *(const float4*)&Bm[(size_t)(m0 + lr) * DIM + lk];
        float4 b1 = *(const float4*)&Bm[(size_t)(m0 + lr) * DIM + lk + 4];
        As[0][lk + 0][lr] = a0.x; As[0][lk + 1][lr] = a0.y;
        As[0][lk + 2][lr] = a0.z; As[0][lk + 3][lr] = a0.w;
        As[0][lk + 4][lr] = a1.x; As[0][lk + 5][lr] = a1.y;
        As[0][lk + 6][lr] = a1.z; As[0][lk + 7][lr] = a1.w;
        Bs[0][lk + 0][lr] = b0.x; Bs[0][lk + 1][lr] = b0.y;
        Bs[0][lk + 2][lr] = b0.z; Bs[0][lk + 3][lr] = b0.w;
        Bs[0][lk + 4][lr] = b1.x; Bs[0][lk + 5][lr] = b1.y;
        Bs[0][lk + 6][lr] = b1.z; Bs[0][lk + 7][lr] = b1.w;
    }
    __syncthreads();

#pragma unroll
    for (int it = 0; it < 8; it++) {
        const int cur = it & 1;
        float4 a0, a1, b0, b1;
        if (it < 7) {
            const int k0 = (it + 1) * 16;
            a0 = *(const float4*)&A [(size_t)(c0 + lr) * DIM + k0 + lk];
            a1 = *(const float4*)&A [(size_t)(c0 + lr) * DIM + k0 + lk + 4];
            b0 = *(const float4*)&Bm[(size_t)(m0 + lr) * DIM + k0 + lk];
            b1 = *(const float4*)&Bm[(size_t)(m0 + lr) * DIM + k0 + lk + 4];
        }

#pragma unroll
        for (int k = 0; k < 16; k++) {
            float a[8], bb[8];
            *(float4*)&a [0] = *(const float4*)&As[cur][k][ty * 8];
            *(float4*)&a [4] = *(const float4*)&As[cur][k][ty * 8 + 4];
            *(float4*)&bb[0] = *(const float4*)&Bs[cur][k][tx * 8];
            *(float4*)&bb[4] = *(const float4*)&Bs[cur][k][tx * 8 + 4];
#pragma unroll
            for (int i = 0; i < 8; i++)
#pragma unroll
                for (int j = 0; j < 8; j++) acc[i][j] += a[i] * bb[j];
        }

        if (it < 7) {
            const int nxt = cur ^ 1;
            As[nxt][lk + 0][lr] = a0.x; As[nxt][lk + 1][lr] = a0.y;
            As[nxt][lk + 2][lr] = a0.z; As[nxt][lk + 3][lr] = a0.w;
            As[nxt][lk + 4][lr] = a1.x; As[nxt][lk + 5][lr] = a1.y;
            As[nxt][lk + 6][lr] = a1.z; As[nxt][lk + 7][lr] = a1.w;
            Bs[nxt][lk + 0][lr] = b0.x; Bs[nxt][lk + 1][lr] = b0.y;
            Bs[nxt][lk + 2][lr] = b0.z; Bs[nxt][lk + 3][lr] = b0.w;
            Bs[nxt][lk + 4][lr] = b1.x; Bs[nxt][lk + 5][lr] = b1.y;
            Bs[nxt][lk + 6][lr] = b1.z; Bs[nxt][lk + 7][lr] = b1.w;
            __syncthreads();
        }
    }

#pragma unroll
    for (int i = 0; i < 8; i++) {
        float* p = &S[(size_t)(c0 + ty * 8 + i) * LSEQ + m0 + tx * 8];
        *(float4*)(p + 0) = make_float4(acc[i][0], acc[i][1], acc[i][2], acc[i][3]);
        *(float4*)(p + 4) = make_float4(acc[i][4], acc[i][5], acc[i][6], acc[i][7]);
    }
}

// ---------------------------------------------------------------------------
// Row softmax over m (row length 2048). One 256-thread block per (b,c) row.
// ---------------------------------------------------------------------------
__global__ __launch_bounds__(256) void softmax_kernel() {
    float* S = g_S + (size_t)blockIdx.x * LSEQ;
    float4* S4 = (float4*)S;
    const int tid = threadIdx.x;

    float4 x0 = S4[tid];
    float4 x1 = S4[tid + 256];

    float mx = fmaxf(fmaxf(fmaxf(x0.x, x0.y), fmaxf(x0.z, x0.w)),
                     fmaxf(fmaxf(x1.x, x1.y), fmaxf(x1.z, x1.w)));
#pragma unroll
    for (int o = 16; o > 0; o >>= 1) mx = fmaxf(mx, __shfl_xor_sync(0xffffffffu, mx, o));

    __shared__ float red[8];
    if ((tid & 31) == 0) red[tid >> 5] = mx;
    __syncthreads();
    mx = red[0];
#pragma unroll
    for (int w = 1; w < 8; w++) mx = fmaxf(mx, red[w]);

    x0.x = __expf(x0.x - mx); x0.y = __expf(x0.y - mx);
    x0.z = __expf(x0.z - mx); x0.w = __expf(x0.w - mx);
    x1.x = __expf(x1.x - mx); x1.y = __expf(x1.y - mx);
    x1.z = __expf(x1.z - mx); x1.w = __expf(x1.w - mx);

    float s = (x0.x + x0.y + x0.z + x0.w) + (x1.x + x1.y + x1.z + x1.w);
#pragma unroll
    for (int o = 16; o > 0; o >>= 1) s += __shfl_xor_sync(0xffffffffu, s, o);

    __syncthreads();  // red reuse
    if ((tid & 31) == 0) red[tid >> 5] = s;
    __syncthreads();
    s = red[0];
#pragma unroll
    for (int w = 1; w < 8; w++) s += red[w];

    const float inv = 1.0f / s;
    x0.x *= inv; x0.y *= inv; x0.z *= inv; x0.w *= inv;
    x1.x *= inv; x1.y *= inv; x1.z *= inv; x1.w *= inv;
    S4[tid] = x0;
    S4[tid + 256] = x1;
}

// ---------------------------------------------------------------------------
// GEMM2 (split-K): part[s][b][m][d] = sum_{c in split s} P[b,c,m] * context[b,c,d]
// M=2048 (m), N=128 (d), K=256 per split. 128x128 tile, BK=16, double-buffered.
// grid: (NSPLIT, LSEQ/128, NB) = 1024 CTAs.
// ---------------------------------------------------------------------------
__global__ __launch_bounds__(256, 2) void gemm2_kernel(const float* __restrict__ ctx) {
    __shared__ float Ps[2][16][128];  // [stage][kc][m]
    __shared__ float Cs[2][16][128];  // [stage][kc][d]

    const int sp = blockIdx.x;
    const int m0 = blockIdx.y * 128;
    const int b  = blockIdx.z;
    const int cbase = sp * KSPLIT;

    const float* P = g_S + (size_t)b * LSEQ * LSEQ;
    const float* C = ctx + (size_t)b * LSEQ * DIM;
    float* PT = g_part + ((size_t)sp * NB + b) * LSEQ * DIM;

    const int tid = threadIdx.x;
    const int kc  = tid >> 4;        // 0..15
    const int q8  = (tid & 15) * 8;  // 0..120
    const int ty  = tid >> 4;
    const int tx  = tid & 15;

    float acc[8][8];
#pragma unroll
    for (int i = 0; i < 8; i++)
#pragma unroll
        for (int j = 0; j < 8; j++) acc[i][j] = 0.0f;

    // prologue
    {
        const int c0 = cbase;
        *(float4*)&Ps[0][kc][q8]     = *(const float4*)&P[(size_t)(c0 + kc) * LSEQ + m0 + q8];
        *(float4*)&Ps[0][kc][q8 + 4] = *(const float4*)&P[(size_t)(c0 + kc) * LSEQ + m0 + q8 + 4];
        *(float4*)&Cs[0][kc][q8]     = *(const float4*)&C[(size_t)(c0 + kc) * DIM + q8];
        *(float4*)&Cs[0][kc][q8 + 4] = *(const float4*)&C[(size_t)(c0 + kc) * DIM + q8 + 4];
    }
    __syncthreads();

#pragma unroll 1
    for (int it = 0; it < KSPLIT / 16; it++) {
        const int cur = it & 1;
        float4 p0, p1, c0v, c1v;
        const bool more = (it < KSPLIT / 16 - 1);
        if (more) {
            const int c0 = cbase + (it + 1) * 16;
            p0  = *(const float4*)&P[(size_t)(c0 + kc) * LSEQ + m0 + q8];
            p1  = *(const float4*)&P[(size_t)(c0 + kc) * LSEQ + m0 + q8 + 4];
            c0v = *(const float4*)&C[(size_t)(c0 + kc) * DIM + q8];
            c1v = *(const float4*)&C[(size_t)(c0 + kc) * DIM + q8 + 4];
        }

#pragma unroll
        for (int k = 0; k < 16; k++) {
            float a[8], bb[8];
            *(float4*)&a [0] = *(const float4*)&Ps[cur][k][ty * 8];
            *(float4*)&a [4] = *(const float4*)&Ps[cur][k][ty * 8 + 4];
            *(float4*)&bb[0] = *(const float4*)&Cs[cur][k][tx * 8];
            *(float4*)&bb[4] = *(const float4*)&Cs[cur][k][tx * 8 + 4];
#pragma unroll
            for (int i = 0; i < 8; i++)
#pragma unroll
                for (int j = 0; j < 8; j++) acc[i][j] += a[i] * bb[j];
        }

        if (more) {
            const int nxt = cur ^ 1;
            *(float4*)&Ps[nxt][kc][q8]     = p0;
            *(float4*)&Ps[nxt][kc][q8 + 4] = p1;
            *(float4*)&Cs[nxt][kc][q8]     = c0v;
            *(float4*)&Cs[nxt][kc][q8 + 4] = c1v;
            __syncthreads();
        }
    }

#pragma unroll
    for (int i = 0; i < 8; i++) {
        const size_t off = (size_t)(m0 + ty * 8 + i) * DIM + tx * 8;
        *(float4*)&PT[off]     = make_float4(acc[i][0], acc[i][1], acc[i][2], acc[i][3]);
        *(float4*)&PT[off + 4] = make_float4(acc[i][4], acc[i][5], acc[i][6], acc[i][7]);
    }
}

// ---------------------------------------------------------------------------
// Reduce: out[b,m,d] = main[b,m,d] - sum_s part[s][b][m][d]   (fixed order)
// ---------------------------------------------------------------------------
__global__ __launch_bounds__(256) void reduce_kernel(const float* __restrict__ mn,
                                                     float* __restrict__ out) {
    const size_t i = (size_t)blockIdx.x * blockDim.x + threadIdx.x;  // float4 index
    const size_t stride4 = (size_t)NB * LSEQ * DIM / 4;
    float4 m = ((const float4*)mn)[i];
    float4 s = make_float4(0.f, 0.f, 0.f, 0.f);
    const float4* p4 = (const float4*)g_part;
#pragma unroll
    for (int sp = 0; sp < NSPLIT; sp++) {
        float4 v = p4[(size_t)sp * stride4 + i];
        s.x += v.x; s.y += v.y; s.z += v.z; s.w += v.w;
    }
    ((float4*)out)[i] = make_float4(m.x - s.x, m.y - s.y, m.z - s.z, m.w - s.w);
}

extern "C" void kernel_launch(void* const* d_in, const int* in_sizes, int n_in,
                              void* d_out, int out_size) {
    (void)in_sizes; (void)n_in; (void)out_size;
    const float* ctx = (const float*)d_in[0];  // context: (8, 2048, 128) f32
    const float* mn  = (const float*)d_in[1];  // main:    (8, 2048, 128) f32
    float* out = (float*)d_out;                // (8, 2048, 128) f32

    dim3 g1(LSEQ / 128, LSEQ / 128, NB);       // 16 x 16 x 8
    gemm1_kernel<<<g1, 256>>>(ctx, mn);

    softmax_kernel<<<NB * LSEQ, 256>>>();

    dim3 g2(NSPLIT, LSEQ / 128, NB);           // 8 x 16 x 8
    gemm2_kernel<<<g2, 256>>>(ctx);

    const int n4 = NB * LSEQ * DIM / 4;        // 524288 float4
    reduce_kernel<<<n4 / 256, 256>>>(mn, out);
}

// round 4
// speedup vs baseline: 1.5074x; 1.2859x over previous
#include <cuda_runtime.h>
#include <cstdint>

#define NB 8
#define LSEQ 2048
#define DIM 128
#define NSPLIT 8
#define KSPLIT (LSEQ / NSPLIT)   // 256

// 128 MiB scratch for the attention matrix S / P.
static __device__ float g_S[(size_t)NB * LSEQ * LSEQ];
// 64 MiB scratch for split-K partials of GEMM2: [split][b][m][d]
static __device__ float g_part[(size_t)NSPLIT * NB * LSEQ * DIM];

__device__ __forceinline__ uint32_t f2tf32(float x) {
    uint32_t r;
    asm("cvt.rna.tf32.f32 %0, %1;" : "=r"(r) : "f"(x));
    return r;
}

#define MMA_TF32(d, a, b0v, b1v)                                               \
    asm volatile(                                                              \
        "mma.sync.aligned.m16n8k8.row.col.f32.tf32.tf32.f32 "                  \
        "{%0,%1,%2,%3}, {%4,%5,%6,%7}, {%8,%9}, {%0,%1,%2,%3};"                \
        : "+f"((d)[0]), "+f"((d)[1]), "+f"((d)[2]), "+f"((d)[3])               \
        : "r"((a)[0]), "r"((a)[1]), "r"((a)[2]), "r"((a)[3]),                  \
          "r"(b0v), "r"(b1v))

// ---------------------------------------------------------------------------
// GEMM1 (mma.sync tf32, 3x split): S[b,c,m] = sum_d ctx[b,c,d]*main[b,m,d]
// CTA tile 128x128, BK=32, 256 threads (8 warps, 2x4), warp tile 64x32.
// smem tiles [row 128][k 36 pad] for A_hi/A_lo/B_hi/B_lo (73728 B dynamic).
// ---------------------------------------------------------------------------
#define PAD1 36
#define T1_BYTES (128 * PAD1 * 4)          // 18432
#define SMEM1_BYTES (4 * T1_BYTES)         // 73728

__global__ __launch_bounds__(256) void gemm1_mma(const float* __restrict__ ctx,
                                                 const float* __restrict__ mn) {
    extern __shared__ uint32_t sm1[];
    uint32_t* sAH = sm1;
    uint32_t* sAL = sm1 + 128 * PAD1;
    uint32_t* sBH = sm1 + 2 * 128 * PAD1;
    uint32_t* sBL = sm1 + 3 * 128 * PAD1;

    const int b  = blockIdx.z;
    const int c0 = blockIdx.y * 128;
    const int m0 = blockIdx.x * 128;

    const float* A = ctx + (size_t)b * LSEQ * DIM + (size_t)c0 * DIM;
    const float* B = mn  + (size_t)b * LSEQ * DIM + (size_t)m0 * DIM;
    float*       S = g_S + (size_t)b * LSEQ * LSEQ;

    const int tid  = threadIdx.x;
    const int wid  = tid >> 5;
    const int lane = tid & 31;
    const int wm   = (wid >> 2) * 64;   // warp m offset (0/64)
    const int wn   = (wid & 3) * 32;    // warp n offset
    const int lr4  = lane >> 2;         // 0..7
    const int lk4  = lane & 3;          // 0..3

    const int r  = tid >> 1;            // load row 0..127
    const int kb = (tid & 1) * 16;      // k half

    float acc[4][4][4];
#pragma unroll
    for (int i = 0; i < 4; i++)
#pragma unroll
        for (int j = 0; j < 4; j++)
#pragma unroll
            for (int q = 0; q < 4; q++) acc[i][j][q] = 0.0f;

    float4 ax[4], bx[4];
#pragma unroll
    for (int q = 0; q < 4; q++) {
        ax[q] = *(const float4*)(A + (size_t)r * DIM + kb + q * 4);
        bx[q] = *(const float4*)(B + (size_t)r * DIM + kb + q * 4);
    }

#pragma unroll 1
    for (int ch = 0; ch < 4; ch++) {
        // convert + store current chunk to smem
#pragma unroll
        for (int q = 0; q < 4; q++) {
            uint32_t h0 = f2tf32(ax[q].x), h1 = f2tf32(ax[q].y),
                     h2 = f2tf32(ax[q].z), h3 = f2tf32(ax[q].w);
            uint4 hv = make_uint4(h0, h1, h2, h3);
            uint4 lv = make_uint4(f2tf32(ax[q].x - __uint_as_float(h0)),
                                  f2tf32(ax[q].y - __uint_as_float(h1)),
                                  f2tf32(ax[q].z - __uint_as_float(h2)),
                                  f2tf32(ax[q].w - __uint_as_float(h3)));
            *(uint4*)&sAH[r * PAD1 + kb + q * 4] = hv;
            *(uint4*)&sAL[r * PAD1 + kb + q * 4] = lv;
            h0 = f2tf32(bx[q].x); h1 = f2tf32(bx[q].y);
            h2 = f2tf32(bx[q].z); h3 = f2tf32(bx[q].w);
            hv = make_uint4(h0, h1, h2, h3);
            lv = make_uint4(f2tf32(bx[q].x - __uint_as_float(h0)),
                            f2tf32(bx[q].y - __uint_as_float(h1)),
                            f2tf32(bx[q].z - __uint_as_float(h2)),
                            f2tf32(bx[q].w - __uint_as_float(h3)));
            *(uint4*)&sBH[r * PAD1 + kb + q * 4] = hv;
            *(uint4*)&sBL[r * PAD1 + kb + q * 4] = lv;
        }
        __syncthreads();

        // prefetch next chunk
        if (ch < 3) {
            const int dk = (ch + 1) * 32;
#pragma unroll
            for (int q = 0; q < 4; q++) {
                ax[q] = *(const float4*)(A + (size_t)r * DIM + dk + kb + q * 4);
                bx[q] = *(const float4*)(B + (size_t)r * DIM + dk + kb + q * 4);
            }
        }

#pragma unroll
        for (int k8 = 0; k8 < 4; k8++) {
            const int k0 = k8 * 8;
            uint32_t ah[4][4], al[4][4];
#pragma unroll
            for (int mt = 0; mt < 4; mt++) {
                const int rr = wm + mt * 16 + lr4;
                const uint32_t* pH = sAH + rr * PAD1 + k0 + lk4;
                const uint32_t* pL = sAL + rr * PAD1 + k0 + lk4;
                ah[mt][0] = pH[0]; ah[mt][1] = pH[8 * PAD1];
                ah[mt][2] = pH[4]; ah[mt][3] = pH[8 * PAD1 + 4];
                al[mt][0] = pL[0]; al[mt][1] = pL[8 * PAD1];
                al[mt][2] = pL[4]; al[mt][3] = pL[8 * PAD1 + 4];
            }
#pragma unroll
            for (int nt = 0; nt < 4; nt++) {
                const int nn = wn + nt * 8 + lr4;
                const uint32_t* qH = sBH + nn * PAD1 + k0 + lk4;
                const uint32_t* qL = sBL + nn * PAD1 + k0 + lk4;
                const uint32_t bh0 = qH[0], bh1 = qH[4];
                const uint32_t bl0 = qL[0], bl1 = qL[4];
#pragma unroll
                for (int mt = 0; mt < 4; mt++) {
                    MMA_TF32(acc[mt][nt], ah[mt], bh0, bh1);
                    MMA_TF32(acc[mt][nt], ah[mt], bl0, bl1);
                    MMA_TF32(acc[mt][nt], al[mt], bh0, bh1);
                }
            }
        }
        if (ch < 3) __syncthreads();
    }

    // epilogue
#pragma unroll
    for (int mt = 0; mt < 4; mt++) {
#pragma unroll
        for (int nt = 0; nt < 4; nt++) {
            const int row = c0 + wm + mt * 16 + lr4;
            const int col = m0 + wn + nt * 8 + 2 * lk4;
            *(float2*)&S[(size_t)row * LSEQ + col] =
                make_float2(acc[mt][nt][0], acc[mt][nt][1]);
            *(float2*)&S[(size_t)(row + 8) * LSEQ + col] =
                make_float2(acc[mt][nt][2], acc[mt][nt][3]);
        }
    }
}

// ---------------------------------------------------------------------------
// Row softmax over m (row length 2048). One 256-thread block per (b,c) row.
// ---------------------------------------------------------------------------
__global__ __launch_bounds__(256) void softmax_kernel() {
    float* S = g_S + (size_t)blockIdx.x * LSEQ;
    float4* S4 = (float4*)S;
    const int tid = threadIdx.x;

    float4 x0 = S4[tid];
    float4 x1 = S4[tid + 256];

    float mx = fmaxf(fmaxf(fmaxf(x0.x, x0.y), fmaxf(x0.z, x0.w)),
                     fmaxf(fmaxf(x1.x, x1.y), fmaxf(x1.z, x1.w)));
#pragma unroll
    for (int o = 16; o > 0; o >>= 1) mx = fmaxf(mx, __shfl_xor_sync(0xffffffffu, mx, o));

    __shared__ float red[8];
    if ((tid & 31) == 0) red[tid >> 5] = mx;
    __syncthreads();
    mx = red[0];
#pragma unroll
    for (int w = 1; w < 8; w++) mx = fmaxf(mx, red[w]);

    x0.x = __expf(x0.x - mx); x0.y = __expf(x0.y - mx);
    x0.z = __expf(x0.z - mx); x0.w = __expf(x0.w - mx);
    x1.x = __expf(x1.x - mx); x1.y = __expf(x1.y - mx);
    x1.z = __expf(x1.z - mx); x1.w = __expf(x1.w - mx);

    float s = (x0.x + x0.y + x0.z + x0.w) + (x1.x + x1.y + x1.z + x1.w);
#pragma unroll
    for (int o = 16; o > 0; o >>= 1) s += __shfl_xor_sync(0xffffffffu, s, o);

    __syncthreads();
    if ((tid & 31) == 0) red[tid >> 5] = s;
    __syncthreads();
    s = red[0];
#pragma unroll
    for (int w = 1; w < 8; w++) s += red[w];

    const float inv = 1.0f / s;
    x0.x *= inv; x0.y *= inv; x0.z *= inv; x0.w *= inv;
    x1.x *= inv; x1.y *= inv; x1.z *= inv; x1.w *= inv;
    S4[tid] = x0;
    S4[tid + 256] = x1;
}

// ---------------------------------------------------------------------------
// GEMM2 (mma.sync tf32, split-K): part[s][b][m][d] = sum_c P[b,c,m]*ctx[b,c,d]
// CTA tile M=128, N=128(d), K=256/split. BK=32, warp tile 64x32.
// smem [k 32][m 132 pad] for P and C (as-loaded layout, no transpose).
// ---------------------------------------------------------------------------
#define PAD2 132

__global__ __launch_bounds__(256) void gemm2_mma(const float* __restrict__ ctx) {
    __shared__ uint32_t sP[32 * PAD2];
    __shared__ uint32_t sC[32 * PAD2];

    const int sp = blockIdx.x;
    const int m0 = blockIdx.y * 128;
    const int b  = blockIdx.z;
    const int cbase = sp * KSPLIT;

    const float* P = g_S + (size_t)b * LSEQ * LSEQ;
    const float* C = ctx + (size_t)b * LSEQ * DIM;
    float* PT = g_part + ((size_t)sp * NB + b) * LSEQ * DIM;

    const int tid  = threadIdx.x;
    const int wid  = tid >> 5;
    const int lane = tid & 31;
    const int wm   = (wid >> 2) * 64;
    const int wn   = (wid & 3) * 32;
    const int lr4  = lane >> 2;
    const int lk4  = lane & 3;

    const int kc = tid >> 3;            // 0..31
    const int mq = (tid & 7) * 16;      // 0..112

    float acc[4][4][4];
#pragma unroll
    for (int i = 0; i < 4; i++)
#pragma unroll
        for (int j = 0; j < 4; j++)
#pragma unroll
            for (int q = 0; q < 4; q++) acc[i][j][q] = 0.0f;

    float4 pv[4], cv[4];
#pragma unroll
    for (int q = 0; q < 4; q++) {
        pv[q] = *(const float4*)(P + (size_t)(cbase + kc) * LSEQ + m0 + mq + q * 4);
        cv[q] = *(const float4*)(C + (size_t)(cbase + kc) * DIM + mq + q * 4);
    }

#pragma unroll 1
    for (int ch = 0; ch < KSPLIT / 32; ch++) {
#pragma unroll
        for (int q = 0; q < 4; q++) {
            *(uint4*)&sP[kc * PAD2 + mq + q * 4] =
                make_uint4(f2tf32(pv[q].x), f2tf32(pv[q].y), f2tf32(pv[q].z), f2tf32(pv[q].w));
            *(uint4*)&sC[kc * PAD2 + mq + q * 4] =
                make_uint4(f2tf32(cv[q].x), f2tf32(cv[q].y), f2tf32(cv[q].z), f2tf32(cv[q].w));
        }
        __syncthreads();

        if (ch < KSPLIT / 32 - 1) {
            const int cb = cbase + (ch + 1) * 32;
#pragma unroll
            for (int q = 0; q < 4; q++) {
                pv[q] = *(const float4*)(P + (size_t)(cb + kc) * LSEQ + m0 + mq + q * 4);
                cv[q] = *(const float4*)(C + (size_t)(cb + kc) * DIM + mq + q * 4);
            }
        }

#pragma unroll
        for (int k8 = 0; k8 < 4; k8++) {
            const int k0 = k8 * 8;
            uint32_t a[4][4];
#pragma unroll
            for (int mt = 0; mt < 4; mt++) {
                const int mm = wm + mt * 16 + lr4;
                const uint32_t* p = sP + (k0 + lk4) * PAD2 + mm;
                a[mt][0] = p[0];
                a[mt][1] = p[8];
                a[mt][2] = p[4 * PAD2];
                a[mt][3] = p[4 * PAD2 + 8];
            }
#pragma unroll
            for (int nt = 0; nt < 4; nt++) {
                const int nn = wn + nt * 8 + lr4;
                const uint32_t* q = sC + (k0 + lk4) * PAD2 + nn;
                const uint32_t b0 = q[0], b1 = q[4 * PAD2];
#pragma unroll
                for (int mt = 0; mt < 4; mt++) MMA_TF32(acc[mt][nt], a[mt], b0, b1);
            }
        }
        if (ch < KSPLIT / 32 - 1) __syncthreads();
    }

#pragma unroll
    for (int mt = 0; mt < 4; mt++) {
#pragma unroll
        for (int nt = 0; nt < 4; nt++) {
            const int row = m0 + wm + mt * 16 + lr4;
            const int col = wn + nt * 8 + 2 * lk4;
            *(float2*)&PT[(size_t)row * DIM + col] =
                make_float2(acc[mt][nt][0], acc[mt][nt][1]);
            *(float2*)&PT[(size_t)(row + 8) * DIM + col] =
                make_float2(acc[mt][nt][2], acc[mt][nt][3]);
        }
    }
}

// ---------------------------------------------------------------------------
// Reduce: out[b,m,d] = main[b,m,d] - sum_s part[s][b][m][d]
// ---------------------------------------------------------------------------
__global__ __launch_bounds__(256) void reduce_kernel(const float* __restrict__ mn,
                                                     float* __restrict__ out) {
    const size_t i = (size_t)blockIdx.x * blockDim.x + threadIdx.x;
    const size_t stride4 = (size_t)NB * LSEQ * DIM / 4;
    float4 m = ((const float4*)mn)[i];
    float4 s = make_float4(0.f, 0.f, 0.f, 0.f);
    const float4* p4 = (const float4*)g_part;
#pragma unroll
    for (int sp = 0; sp < NSPLIT; sp++) {
        float4 v = p4[(size_t)sp * stride4 + i];
        s.x += v.x; s.y += v.y; s.z += v.z; s.w += v.w;
    }
    ((float4*)out)[i] = make_float4(m.x - s.x, m.y - s.y, m.z - s.z, m.w - s.w);
}

extern "C" void kernel_launch(void* const* d_in, const int* in_sizes, int n_in,
                              void* d_out, int out_size) {
    (void)in_sizes; (void)n_in; (void)out_size;
    const float* ctx = (const float*)d_in[0];  // context: (8, 2048, 128) f32
    const float* mn  = (const float*)d_in[1];  // main:    (8, 2048, 128) f32
    float* out = (float*)d_out;                // (8, 2048, 128) f32

    cudaFuncSetAttribute(gemm1_mma, cudaFuncAttributeMaxDynamicSharedMemorySize, SMEM1_BYTES);

    dim3 g1(LSEQ / 128, LSEQ / 128, NB);       // 16 x 16 x 8
    gemm1_mma<<<g1, 256, SMEM1_BYTES>>>(ctx, mn);

    softmax_kernel<<<NB * LSEQ, 256>>>();

    dim3 g2(NSPLIT, LSEQ / 128, NB);           // 8 x 16 x 8
    gemm2_mma<<<g2, 256>>>(ctx);

    const int n4 = NB * LSEQ * DIM / 4;        // 524288 float4
    reduce_kernel<<<n4 / 256, 256>>>(mn, out);
}

// round 5
// speedup vs baseline: 1.6955x; 1.1248x over previous
#include <cuda_runtime.h>
#include <cstdint>

#define NB 8
#define LSEQ 2048
#define DIM 128
#define NSPLIT 8
#define KSPLIT (LSEQ / NSPLIT)   // 256

// 128 MiB scratch for the attention logits S (raw, pre-softmax).
static __device__ float g_S[(size_t)NB * LSEQ * LSEQ];
// 64 MiB scratch for split-K partials of GEMM2: [split][b][m][d]
static __device__ float g_part[(size_t)NSPLIT * NB * LSEQ * DIM];
// per-(b,c)-row softmax stats: x = rowmax, y = 1/sum(exp)
static __device__ float2 g_stats[(size_t)NB * LSEQ];

__device__ __forceinline__ uint32_t f2tf32(float x) {
    uint32_t r;
    asm("cvt.rna.tf32.f32 %0, %1;" : "=r"(r) : "f"(x));
    return r;
}

#define MMA_TF32(d, a, b0v, b1v)                                               \
    asm volatile(                                                              \
        "mma.sync.aligned.m16n8k8.row.col.f32.tf32.tf32.f32 "                  \
        "{%0,%1,%2,%3}, {%4,%5,%6,%7}, {%8,%9}, {%0,%1,%2,%3};"                \
        : "+f"((d)[0]), "+f"((d)[1]), "+f"((d)[2]), "+f"((d)[3])               \
        : "r"((a)[0]), "r"((a)[1]), "r"((a)[2]), "r"((a)[3]),                  \
          "r"(b0v), "r"(b1v))

// ---------------------------------------------------------------------------
// GEMM1 (mma.sync tf32, 3x split): S[b,c,m] = sum_d ctx[b,c,d]*main[b,m,d]
// CTA tile 128x128, BK=32, 256 threads (8 warps), warp tile 64x32, occ 2.
// Single-buffered smem; cross-CTA overlap hides the load phase.
// ---------------------------------------------------------------------------
#define PAD1 36
#define SMEM1_BYTES (4 * 128 * PAD1 * 4)   // 73728

__global__ __launch_bounds__(256, 2) void gemm1_mma(const float* __restrict__ ctx,
                                                    const float* __restrict__ mn) {
    extern __shared__ uint32_t sm1[];
    uint32_t* sAH = sm1;
    uint32_t* sAL = sm1 + 128 * PAD1;
    uint32_t* sBH = sm1 + 2 * 128 * PAD1;
    uint32_t* sBL = sm1 + 3 * 128 * PAD1;

    const int b  = blockIdx.z;
    const int c0 = blockIdx.y * 128;
    const int m0 = blockIdx.x * 128;

    const float* A = ctx + (size_t)b * LSEQ * DIM + (size_t)c0 * DIM;
    const float* B = mn  + (size_t)b * LSEQ * DIM + (size_t)m0 * DIM;
    float*       S = g_S + (size_t)b * LSEQ * LSEQ;

    const int tid  = threadIdx.x;
    const int wid  = tid >> 5;
    const int lane = tid & 31;
    const int wm   = (wid >> 2) * 64;
    const int wn   = (wid & 3) * 32;
    const int lr4  = lane >> 2;
    const int lk4  = lane & 3;

    const int r  = tid >> 1;
    const int kb = (tid & 1) * 16;

    float acc[4][4][4];
#pragma unroll
    for (int i = 0; i < 4; i++)
#pragma unroll
        for (int j = 0; j < 4; j++)
#pragma unroll
            for (int q = 0; q < 4; q++) acc[i][j][q] = 0.0f;

#pragma unroll 1
    for (int ch = 0; ch < 4; ch++) {
        const int dk = ch * 32;
        __syncthreads();  // previous chunk's consumers done
#pragma unroll
        for (int q = 0; q < 4; q++) {
            float4 av = *(const float4*)(A + (size_t)r * DIM + dk + kb + q * 4);
            float4 bv = *(const float4*)(B + (size_t)r * DIM + dk + kb + q * 4);
            uint32_t h0 = f2tf32(av.x), h1 = f2tf32(av.y),
                     h2 = f2tf32(av.z), h3 = f2tf32(av.w);
            *(uint4*)&sAH[r * PAD1 + kb + q * 4] = make_uint4(h0, h1, h2, h3);
            *(uint4*)&sAL[r * PAD1 + kb + q * 4] =
                make_uint4(__float_as_uint(av.x - __uint_as_float(h0)),
                           __float_as_uint(av.y - __uint_as_float(h1)),
                           __float_as_uint(av.z - __uint_as_float(h2)),
                           __float_as_uint(av.w - __uint_as_float(h3)));
            h0 = f2tf32(bv.x); h1 = f2tf32(bv.y);
            h2 = f2tf32(bv.z); h3 = f2tf32(bv.w);
            *(uint4*)&sBH[r * PAD1 + kb + q * 4] = make_uint4(h0, h1, h2, h3);
            *(uint4*)&sBL[r * PAD1 + kb + q * 4] =
                make_uint4(__float_as_uint(bv.x - __uint_as_float(h0)),
                           __float_as_uint(bv.y - __uint_as_float(h1)),
                           __float_as_uint(bv.z - __uint_as_float(h2)),
                           __float_as_uint(bv.w - __uint_as_float(h3)));
        }
        __syncthreads();

#pragma unroll
        for (int k8 = 0; k8 < 4; k8++) {
            const int k0 = k8 * 8;
            uint32_t ah[4][4], al[4][4];
#pragma unroll
            for (int mt = 0; mt < 4; mt++) {
                const int rr = wm + mt * 16 + lr4;
                const uint32_t* pH = sAH + rr * PAD1 + k0 + lk4;
                const uint32_t* pL = sAL + rr * PAD1 + k0 + lk4;
                ah[mt][0] = pH[0]; ah[mt][1] = pH[8 * PAD1];
                ah[mt][2] = pH[4]; ah[mt][3] = pH[8 * PAD1 + 4];
                al[mt][0] = pL[0]; al[mt][1] = pL[8 * PAD1];
                al[mt][2] = pL[4]; al[mt][3] = pL[8 * PAD1 + 4];
            }
#pragma unroll
            for (int nt = 0; nt < 4; nt++) {
                const int nn = wn + nt * 8 + lr4;
                const uint32_t* qH = sBH + nn * PAD1 + k0 + lk4;
                const uint32_t* qL = sBL + nn * PAD1 + k0 + lk4;
                const uint32_t bh0 = qH[0], bh1 = qH[4];
                const uint32_t bl0 = qL[0], bl1 = qL[4];
#pragma unroll
                for (int mt = 0; mt < 4; mt++) {
                    MMA_TF32(acc[mt][nt], ah[mt], bh0, bh1);
                    MMA_TF32(acc[mt][nt], ah[mt], bl0, bl1);
                    MMA_TF32(acc[mt][nt], al[mt], bh0, bh1);
                }
            }
        }
    }

#pragma unroll
    for (int mt = 0; mt < 4; mt++) {
#pragma unroll
        for (int nt = 0; nt < 4; nt++) {
            const int row = c0 + wm + mt * 16 + lr4;
            const int col = m0 + wn + nt * 8 + 2 * lk4;
            *(float2*)&S[(size_t)row * LSEQ + col] =
                make_float2(acc[mt][nt][0], acc[mt][nt][1]);
            *(float2*)&S[(size_t)(row + 8) * LSEQ + col] =
                make_float2(acc[mt][nt][2], acc[mt][nt][3]);
        }
    }
}

// ---------------------------------------------------------------------------
// Stats: per (b,c) row of S, compute rowmax and 1/sum(exp(x-mx)).
// One 256-thread block per row.
// ---------------------------------------------------------------------------
__global__ __launch_bounds__(256) void stats_kernel() {
    const float4* S4 = (const float4*)(g_S + (size_t)blockIdx.x * LSEQ);
    const int tid = threadIdx.x;

    float4 x0 = S4[tid];
    float4 x1 = S4[tid + 256];

    float mx = fmaxf(fmaxf(fmaxf(x0.x, x0.y), fmaxf(x0.z, x0.w)),
                     fmaxf(fmaxf(x1.x, x1.y), fmaxf(x1.z, x1.w)));
#pragma unroll
    for (int o = 16; o > 0; o >>= 1) mx = fmaxf(mx, __shfl_xor_sync(0xffffffffu, mx, o));

    __shared__ float red[8];
    if ((tid & 31) == 0) red[tid >> 5] = mx;
    __syncthreads();
    mx = red[0];
#pragma unroll
    for (int w = 1; w < 8; w++) mx = fmaxf(mx, red[w]);

    float s = __expf(x0.x - mx) + __expf(x0.y - mx) + __expf(x0.z - mx) + __expf(x0.w - mx)
            + __expf(x1.x - mx) + __expf(x1.y - mx) + __expf(x1.z - mx) + __expf(x1.w - mx);
#pragma unroll
    for (int o = 16; o > 0; o >>= 1) s += __shfl_xor_sync(0xffffffffu, s, o);

    __syncthreads();
    if ((tid & 31) == 0) red[tid >> 5] = s;
    __syncthreads();
    s = red[0];
#pragma unroll
    for (int w = 1; w < 8; w++) s += red[w];

    if (tid == 0) g_stats[blockIdx.x] = make_float2(mx, 1.0f / s);
}

// ---------------------------------------------------------------------------
// GEMM2 (mma.sync tf32, split-K, fused softmax):
//   part[s][b][m][d] = sum_c exp(S[b,c,m]-mx[c])*inv[c] * ctx[b,c,d]
// CTA tile M=128, N=128(d), K=256/split. BK=32. Softmax applied at smem store.
// ---------------------------------------------------------------------------
#define PAD2 132

__global__ __launch_bounds__(256, 2) void gemm2_mma(const float* __restrict__ ctx) {
    __shared__ uint32_t sP[32 * PAD2];
    __shared__ uint32_t sC[32 * PAD2];

    const int sp = blockIdx.x;
    const int m0 = blockIdx.y * 128;
    const int b  = blockIdx.z;
    const int cbase = sp * KSPLIT;

    const float* P = g_S + (size_t)b * LSEQ * LSEQ;
    const float* C = ctx + (size_t)b * LSEQ * DIM;
    float* PT = g_part + ((size_t)sp * NB + b) * LSEQ * DIM;

    const int tid  = threadIdx.x;
    const int wid  = tid >> 5;
    const int lane = tid & 31;
    const int wm   = (wid >> 2) * 64;
    const int wn   = (wid & 3) * 32;
    const int lr4  = lane >> 2;
    const int lk4  = lane & 3;

    const int kc = tid >> 3;            // 0..31
    const int mq = (tid & 7) * 16;      // 0..112

    float acc[4][4][4];
#pragma unroll
    for (int i = 0; i < 4; i++)
#pragma unroll
        for (int j = 0; j < 4; j++)
#pragma unroll
            for (int q = 0; q < 4; q++) acc[i][j][q] = 0.0f;

#pragma unroll 1
    for (int ch = 0; ch < KSPLIT / 32; ch++) {
        const int crow = cbase + ch * 32 + kc;
        const float2 st = g_stats[(size_t)b * LSEQ + crow];
        __syncthreads();
#pragma unroll
        for (int q = 0; q < 4; q++) {
            float4 pv = *(const float4*)(P + (size_t)crow * LSEQ + m0 + mq + q * 4);
            float4 cv = *(const float4*)(C + (size_t)crow * DIM + mq + q * 4);
            pv.x = __expf(pv.x - st.x) * st.y;
            pv.y = __expf(pv.y - st.x) * st.y;
            pv.z = __expf(pv.z - st.x) * st.y;
            pv.w = __expf(pv.w - st.x) * st.y;
            *(uint4*)&sP[kc * PAD2 + mq + q * 4] =
                make_uint4(f2tf32(pv.x), f2tf32(pv.y), f2tf32(pv.z), f2tf32(pv.w));
            *(uint4*)&sC[kc * PAD2 + mq + q * 4] =
                make_uint4(f2tf32(cv.x), f2tf32(cv.y), f2tf32(cv.z), f2tf32(cv.w));
        }
        __syncthreads();

#pragma unroll
        for (int k8 = 0; k8 < 4; k8++) {
            const int k0 = k8 * 8;
            uint32_t a[4][4];
#pragma unroll
            for (int mt = 0; mt < 4; mt++) {
                const int mm = wm + mt * 16 + lr4;
                const uint32_t* p = sP + (k0 + lk4) * PAD2 + mm;
                a[mt][0] = p[0];
                a[mt][1] = p[8];
                a[mt][2] = p[4 * PAD2];
                a[mt][3] = p[4 * PAD2 + 8];
            }
#pragma unroll
            for (int nt = 0; nt < 4; nt++) {
                const int nn = wn + nt * 8 + lr4;
                const uint32_t* q = sC + (k0 + lk4) * PAD2 + nn;
                const uint32_t b0 = q[0], b1 = q[4 * PAD2];
#pragma unroll
                for (int mt = 0; mt < 4; mt++) MMA_TF32(acc[mt][nt], a[mt], b0, b1);
            }
        }
    }

#pragma unroll
    for (int mt = 0; mt < 4; mt++) {
#pragma unroll
        for (int nt = 0; nt < 4; nt++) {
            const int row = m0 + wm + mt * 16 + lr4;
            const int col = wn + nt * 8 + 2 * lk4;
            *(float2*)&PT[(size_t)row * DIM + col] =
                make_float2(acc[mt][nt][0], acc[mt][nt][1]);
            *(float2*)&PT[(size_t)(row + 8) * DIM + col] =
                make_float2(acc[mt][nt][2], acc[mt][nt][3]);
        }
    }
}

// ---------------------------------------------------------------------------
// Reduce: out[b,m,d] = main[b,m,d] - sum_s part[s][b][m][d]
// ---------------------------------------------------------------------------
__global__ __launch_bounds__(256) void reduce_kernel(const float* __restrict__ mn,
                                                     float* __restrict__ out) {
    const size_t i = (size_t)blockIdx.x * blockDim.x + threadIdx.x;
    const size_t stride4 = (size_t)NB * LSEQ * DIM / 4;
    float4 m = ((const float4*)mn)[i];
    float4 s = make_float4(0.f, 0.f, 0.f, 0.f);
    const float4* p4 = (const float4*)g_part;
#pragma unroll
    for (int sp = 0; sp < NSPLIT; sp++) {
        float4 v = p4[(size_t)sp * stride4 + i];
        s.x += v.x; s.y += v.y; s.z += v.z; s.w += v.w;
    }
    ((float4*)out)[i] = make_float4(m.x - s.x, m.y - s.y, m.z - s.z, m.w - s.w);
}

extern "C" void kernel_launch(void* const* d_in, const int* in_sizes, int n_in,
                              void* d_out, int out_size) {
    (void)in_sizes; (void)n_in; (void)out_size;
    const float* ctx = (const float*)d_in[0];  // context: (8, 2048, 128) f32
    const float* mn  = (const float*)d_in[1];  // main:    (8, 2048, 128) f32
    float* out = (float*)d_out;                // (8, 2048, 128) f32

    cudaFuncSetAttribute(gemm1_mma, cudaFuncAttributeMaxDynamicSharedMemorySize, SMEM1_BYTES);

    dim3 g1(LSEQ / 128, LSEQ / 128, NB);       // 16 x 16 x 8
    gemm1_mma<<<g1, 256, SMEM1_BYTES>>>(ctx, mn);

    stats_kernel<<<NB * LSEQ, 256>>>();

    dim3 g2(NSPLIT, LSEQ / 128, NB);           // 8 x 16 x 8
    gemm2_mma<<<g2, 256>>>(ctx);

    const int n4 = NB * LSEQ * DIM / 4;        // 524288 float4
    reduce_kernel<<<n4 / 256, 256>>>(mn, out);
}

// round 6
// speedup vs baseline: 1.7711x; 1.0446x over previous
#include <cuda_runtime.h>
#include <cstdint>

#define NB 8
#define LSEQ 2048
#define DIM 128
#define NSPLIT 8
#define KSPLIT (LSEQ / NSPLIT)   // 256

// 128 MiB scratch: E[b,c,m] = exp(S[b,c,m])  (unnormalized softmax numerator)
static __device__ float g_S[(size_t)NB * LSEQ * LSEQ];
// 64 MiB scratch for split-K partials of GEMM2: [split][b][m][d]
static __device__ float g_part[(size_t)NSPLIT * NB * LSEQ * DIM];
// per-(b,c)-row partial sums of E over each of the 16 m-tiles
static __device__ float g_esum[(size_t)NB * LSEQ * 16];
// per-(b,c)-row 1/sum(E)
static __device__ float g_inv[(size_t)NB * LSEQ];

__device__ __forceinline__ uint32_t f2tf32(float x) {
    uint32_t r;
    asm("cvt.rna.tf32.f32 %0, %1;" : "=r"(r) : "f"(x));
    return r;
}

#define MMA_TF32(d, a, b0v, b1v)                                               \
    asm volatile(                                                              \
        "mma.sync.aligned.m16n8k8.row.col.f32.tf32.tf32.f32 "                  \
        "{%0,%1,%2,%3}, {%4,%5,%6,%7}, {%8,%9}, {%0,%1,%2,%3};"                \
        : "+f"((d)[0]), "+f"((d)[1]), "+f"((d)[2]), "+f"((d)[3])               \
        : "r"((a)[0]), "r"((a)[1]), "r"((a)[2]), "r"((a)[3]),                  \
          "r"(b0v), "r"(b1v))

// ---------------------------------------------------------------------------
// GEMM1 (mma.sync tf32, 3x split) + fused exp + row-sum partials:
//   E[b,c,m] = exp(sum_d ctx[b,c,d]*main[b,m,d])
//   g_esum[b,c][mtile] = sum over this CTA's 128 m-columns of E
// CTA tile 128x128, BK=32, 256 threads, warp tile 64x32, occ 2.
// ---------------------------------------------------------------------------
#define PAD1 36
#define SMEM1_BYTES (4 * 128 * PAD1 * 4)   // 73728

__global__ __launch_bounds__(256, 2) void gemm1_mma(const float* __restrict__ ctx,
                                                    const float* __restrict__ mn) {
    extern __shared__ uint32_t sm1[];
    uint32_t* sAH = sm1;
    uint32_t* sAL = sm1 + 128 * PAD1;
    uint32_t* sBH = sm1 + 2 * 128 * PAD1;
    uint32_t* sBL = sm1 + 3 * 128 * PAD1;

    const int b  = blockIdx.z;
    const int c0 = blockIdx.y * 128;
    const int m0 = blockIdx.x * 128;

    const float* A = ctx + (size_t)b * LSEQ * DIM + (size_t)c0 * DIM;
    const float* B = mn  + (size_t)b * LSEQ * DIM + (size_t)m0 * DIM;
    float*       E = g_S + (size_t)b * LSEQ * LSEQ;

    const int tid  = threadIdx.x;
    const int wid  = tid >> 5;
    const int lane = tid & 31;
    const int wm   = (wid >> 2) * 64;
    const int wn   = (wid & 3) * 32;
    const int lr4  = lane >> 2;
    const int lk4  = lane & 3;

    const int r  = tid >> 1;
    const int kb = (tid & 1) * 16;

    float acc[4][4][4];
#pragma unroll
    for (int i = 0; i < 4; i++)
#pragma unroll
        for (int j = 0; j < 4; j++)
#pragma unroll
            for (int q = 0; q < 4; q++) acc[i][j][q] = 0.0f;

#pragma unroll 1
    for (int ch = 0; ch < 4; ch++) {
        const int dk = ch * 32;
        __syncthreads();
#pragma unroll
        for (int q = 0; q < 4; q++) {
            float4 av = *(const float4*)(A + (size_t)r * DIM + dk + kb + q * 4);
            float4 bv = *(const float4*)(B + (size_t)r * DIM + dk + kb + q * 4);
            uint32_t h0 = f2tf32(av.x), h1 = f2tf32(av.y),
                     h2 = f2tf32(av.z), h3 = f2tf32(av.w);
            *(uint4*)&sAH[r * PAD1 + kb + q * 4] = make_uint4(h0, h1, h2, h3);
            *(uint4*)&sAL[r * PAD1 + kb + q * 4] =
                make_uint4(__float_as_uint(av.x - __uint_as_float(h0)),
                           __float_as_uint(av.y - __uint_as_float(h1)),
                           __float_as_uint(av.z - __uint_as_float(h2)),
                           __float_as_uint(av.w - __uint_as_float(h3)));
            h0 = f2tf32(bv.x); h1 = f2tf32(bv.y);
            h2 = f2tf32(bv.z); h3 = f2tf32(bv.w);
            *(uint4*)&sBH[r * PAD1 + kb + q * 4] = make_uint4(h0, h1, h2, h3);
            *(uint4*)&sBL[r * PAD1 + kb + q * 4] =
                make_uint4(__float_as_uint(bv.x - __uint_as_float(h0)),
                           __float_as_uint(bv.y - __uint_as_float(h1)),
                           __float_as_uint(bv.z - __uint_as_float(h2)),
                           __float_as_uint(bv.w - __uint_as_float(h3)));
        }
        __syncthreads();

#pragma unroll
        for (int k8 = 0; k8 < 4; k8++) {
            const int k0 = k8 * 8;
            uint32_t ah[4][4], al[4][4];
#pragma unroll
            for (int mt = 0; mt < 4; mt++) {
                const int rr = wm + mt * 16 + lr4;
                const uint32_t* pH = sAH + rr * PAD1 + k0 + lk4;
                const uint32_t* pL = sAL + rr * PAD1 + k0 + lk4;
                ah[mt][0] = pH[0]; ah[mt][1] = pH[8 * PAD1];
                ah[mt][2] = pH[4]; ah[mt][3] = pH[8 * PAD1 + 4];
                al[mt][0] = pL[0]; al[mt][1] = pL[8 * PAD1];
                al[mt][2] = pL[4]; al[mt][3] = pL[8 * PAD1 + 4];
            }
#pragma unroll
            for (int nt = 0; nt < 4; nt++) {
                const int nn = wn + nt * 8 + lr4;
                const uint32_t* qH = sBH + nn * PAD1 + k0 + lk4;
                const uint32_t* qL = sBL + nn * PAD1 + k0 + lk4;
                const uint32_t bh0 = qH[0], bh1 = qH[4];
                const uint32_t bl0 = qL[0], bl1 = qL[4];
#pragma unroll
                for (int mt = 0; mt < 4; mt++) {
                    MMA_TF32(acc[mt][nt], ah[mt], bh0, bh1);
                    MMA_TF32(acc[mt][nt], ah[mt], bl0, bl1);
                    MMA_TF32(acc[mt][nt], al[mt], bh0, bh1);
                }
            }
        }
    }

    // ---- epilogue: exp, store E, accumulate deterministic row partial sums
    __syncthreads();                       // smem tiles free for reuse
    float* s_part = (float*)sm1;           // [4 warp-cols][128 rows]

#pragma unroll
    for (int mt = 0; mt < 4; mt++) {
        float s0 = 0.f, s1 = 0.f;
#pragma unroll
        for (int nt = 0; nt < 4; nt++) {
            const float e0 = __expf(acc[mt][nt][0]);
            const float e1 = __expf(acc[mt][nt][1]);
            const float e2 = __expf(acc[mt][nt][2]);
            const float e3 = __expf(acc[mt][nt][3]);
            const int row = c0 + wm + mt * 16 + lr4;
            const int col = m0 + wn + nt * 8 + 2 * lk4;
            *(float2*)&E[(size_t)row * LSEQ + col]       = make_float2(e0, e1);
            *(float2*)&E[(size_t)(row + 8) * LSEQ + col] = make_float2(e2, e3);
            s0 += e0 + e1;
            s1 += e2 + e3;
        }
        s0 += __shfl_xor_sync(0xffffffffu, s0, 1);
        s0 += __shfl_xor_sync(0xffffffffu, s0, 2);
        s1 += __shfl_xor_sync(0xffffffffu, s1, 1);
        s1 += __shfl_xor_sync(0xffffffffu, s1, 2);
        if (lk4 == 0) {
            s_part[(wid & 3) * 128 + wm + mt * 16 + lr4]     = s0;
            s_part[(wid & 3) * 128 + wm + mt * 16 + lr4 + 8] = s1;
        }
    }
    __syncthreads();
    if (tid < 128) {
        const float tot = ((s_part[tid] + s_part[128 + tid]) +
                           (s_part[256 + tid] + s_part[384 + tid]));
        g_esum[((size_t)b * LSEQ + c0 + tid) * 16 + blockIdx.x] = tot;
    }
}

// ---------------------------------------------------------------------------
// inv: g_inv[row] = 1 / sum_{t<16} g_esum[row][t]
// ---------------------------------------------------------------------------
__global__ __launch_bounds__(256) void inv_kernel() {
    const int i = blockIdx.x * 256 + threadIdx.x;   // 0..NB*LSEQ-1
    const float4* p = (const float4*)(g_esum + (size_t)i * 16);
    float4 a = p[0], b4 = p[1], c = p[2], d = p[3];
    const float tot = (((a.x + a.y) + (a.z + a.w)) + ((b4.x + b4.y) + (b4.z + b4.w)))
                    + (((c.x + c.y) + (c.z + c.w)) + ((d.x + d.y) + (d.z + d.w)));
    g_inv[i] = 1.0f / tot;
}

// ---------------------------------------------------------------------------
// GEMM2 (mma.sync tf32, split-K):
//   part[s][b][m][d] = sum_c (E[b,c,m]*inv[b,c]) * ctx[b,c,d]
// ---------------------------------------------------------------------------
#define PAD2 132

__global__ __launch_bounds__(256, 2) void gemm2_mma(const float* __restrict__ ctx) {
    __shared__ uint32_t sP[32 * PAD2];
    __shared__ uint32_t sC[32 * PAD2];

    const int sp = blockIdx.x;
    const int m0 = blockIdx.y * 128;
    const int b  = blockIdx.z;
    const int cbase = sp * KSPLIT;

    const float* Ebuf = g_S + (size_t)b * LSEQ * LSEQ;
    const float* C = ctx + (size_t)b * LSEQ * DIM;
    float* PT = g_part + ((size_t)sp * NB + b) * LSEQ * DIM;

    const int tid  = threadIdx.x;
    const int wid  = tid >> 5;
    const int lane = tid & 31;
    const int wm   = (wid >> 2) * 64;
    const int wn   = (wid & 3) * 32;
    const int lr4  = lane >> 2;
    const int lk4  = lane & 3;

    const int kc = tid >> 3;            // 0..31
    const int mq = (tid & 7) * 16;      // 0..112

    float acc[4][4][4];
#pragma unroll
    for (int i = 0; i < 4; i++)
#pragma unroll
        for (int j = 0; j < 4; j++)
#pragma unroll
            for (int q = 0; q < 4; q++) acc[i][j][q] = 0.0f;

#pragma unroll 1
    for (int ch = 0; ch < KSPLIT / 32; ch++) {
        const int crow = cbase + ch * 32 + kc;
        const float inv = g_inv[(size_t)b * LSEQ + crow];
        __syncthreads();
#pragma unroll
        for (int q = 0; q < 4; q++) {
            float4 pv = *(const float4*)(Ebuf + (size_t)crow * LSEQ + m0 + mq + q * 4);
            float4 cv = *(const float4*)(C + (size_t)crow * DIM + mq + q * 4);
            pv.x *= inv; pv.y *= inv; pv.z *= inv; pv.w *= inv;
            *(uint4*)&sP[kc * PAD2 + mq + q * 4] =
                make_uint4(f2tf32(pv.x), f2tf32(pv.y), f2tf32(pv.z), f2tf32(pv.w));
            *(uint4*)&sC[kc * PAD2 + mq + q * 4] =
                make_uint4(f2tf32(cv.x), f2tf32(cv.y), f2tf32(cv.z), f2tf32(cv.w));
        }
        __syncthreads();

#pragma unroll
        for (int k8 = 0; k8 < 4; k8++) {
            const int k0 = k8 * 8;
            uint32_t a[4][4];
#pragma unroll
            for (int mt = 0; mt < 4; mt++) {
                const int mm = wm + mt * 16 + lr4;
                const uint32_t* p = sP + (k0 + lk4) * PAD2 + mm;
                a[mt][0] = p[0];
                a[mt][1] = p[8];
                a[mt][2] = p[4 * PAD2];
                a[mt][3] = p[4 * PAD2 + 8];
            }
#pragma unroll
            for (int nt = 0; nt < 4; nt++) {
                const int nn = wn + nt * 8 + lr4;
                const uint32_t* q = sC + (k0 + lk4) * PAD2 + nn;
                const uint32_t b0 = q[0], b1 = q[4 * PAD2];
#pragma unroll
                for (int mt = 0; mt < 4; mt++) MMA_TF32(acc[mt][nt], a[mt], b0, b1);
            }
        }
    }

#pragma unroll
    for (int mt = 0; mt < 4; mt++) {
#pragma unroll
        for (int nt = 0; nt < 4; nt++) {
            const int row = m0 + wm + mt * 16 + lr4;
            const int col = wn + nt * 8 + 2 * lk4;
            *(float2*)&PT[(size_t)row * DIM + col] =
                make_float2(acc[mt][nt][0], acc[mt][nt][1]);
            *(float2*)&PT[(size_t)(row + 8) * DIM + col] =
                make_float2(acc[mt][nt][2], acc[mt][nt][3]);
        }
    }
}

// ---------------------------------------------------------------------------
// Reduce: out[b,m,d] = main[b,m,d] - sum_s part[s][b][m][d]
// ---------------------------------------------------------------------------
__global__ __launch_bounds__(256) void reduce_kernel(const float* __restrict__ mn,
                                                     float* __restrict__ out) {
    const size_t i = (size_t)blockIdx.x * blockDim.x + threadIdx.x;
    const size_t stride4 = (size_t)NB * LSEQ * DIM / 4;
    float4 m = ((const float4*)mn)[i];
    float4 s = make_float4(0.f, 0.f, 0.f, 0.f);
    const float4* p4 = (const float4*)g_part;
#pragma unroll
    for (int sp = 0; sp < NSPLIT; sp++) {
        float4 v = p4[(size_t)sp * stride4 + i];
        s.x += v.x; s.y += v.y; s.z += v.z; s.w += v.w;
    }
    ((float4*)out)[i] = make_float4(m.x - s.x, m.y - s.y, m.z - s.z, m.w - s.w);
}

extern "C" void kernel_launch(void* const* d_in, const int* in_sizes, int n_in,
                              void* d_out, int out_size) {
    (void)in_sizes; (void)n_in; (void)out_size;
    const float* ctx = (const float*)d_in[0];  // context: (8, 2048, 128) f32
    const float* mn  = (const float*)d_in[1];  // main:    (8, 2048, 128) f32
    float* out = (float*)d_out;                // (8, 2048, 128) f32

    cudaFuncSetAttribute(gemm1_mma, cudaFuncAttributeMaxDynamicSharedMemorySize, SMEM1_BYTES);

    dim3 g1(LSEQ / 128, LSEQ / 128, NB);       // 16 x 16 x 8
    gemm1_mma<<<g1, 256, SMEM1_BYTES>>>(ctx, mn);

    inv_kernel<<<NB * LSEQ / 256, 256>>>();

    dim3 g2(NSPLIT, LSEQ / 128, NB);           // 8 x 16 x 8
    gemm2_mma<<<g2, 256>>>(ctx);

    const int n4 = NB * LSEQ * DIM / 4;        // 524288 float4
    reduce_kernel<<<n4 / 256, 256>>>(mn, out);
}

// round 7
// speedup vs baseline: 2.1374x; 1.2068x over previous
#include <cuda_runtime.h>
#include <cuda_bf16.h>
#include <cstdint>

#define NB 8
#define LSEQ 2048
#define DIM 128
#define NSPLIT 8
#define KSPLIT (LSEQ / NSPLIT)   // 256

// 128 MiB scratch: E[b,c,m] = exp(S[b,c,m])
static __device__ float g_S[(size_t)NB * LSEQ * LSEQ];
// 64 MiB scratch for split-K partials of GEMM2: [split][b][m][d]
static __device__ float g_part[(size_t)NSPLIT * NB * LSEQ * DIM];
// per-(b,c)-row partial sums of E over each of the 16 m-tiles
static __device__ float g_esum[(size_t)NB * LSEQ * 16];
// per-(b,c)-row 1/sum(E)
static __device__ float g_inv[(size_t)NB * LSEQ];

__device__ __forceinline__ uint32_t f2tf32(float x) {
    uint32_t r;
    asm("cvt.rna.tf32.f32 %0, %1;" : "=r"(r) : "f"(x));
    return r;
}

#define MMA_TF32(d, a, b0v, b1v)                                               \
    asm volatile(                                                              \
        "mma.sync.aligned.m16n8k8.row.col.f32.tf32.tf32.f32 "                  \
        "{%0,%1,%2,%3}, {%4,%5,%6,%7}, {%8,%9}, {%0,%1,%2,%3};"                \
        : "+f"((d)[0]), "+f"((d)[1]), "+f"((d)[2]), "+f"((d)[3])               \
        : "r"((a)[0]), "r"((a)[1]), "r"((a)[2]), "r"((a)[3]),                  \
          "r"(b0v), "r"(b1v))

#define MMA_BF16(d, a, b0v, b1v)                                               \
    asm volatile(                                                              \
        "mma.sync.aligned.m16n8k16.row.col.f32.bf16.bf16.f32 "                 \
        "{%0,%1,%2,%3}, {%4,%5,%6,%7}, {%8,%9}, {%0,%1,%2,%3};"                \
        : "+f"((d)[0]), "+f"((d)[1]), "+f"((d)[2]), "+f"((d)[3])               \
        : "r"((a)[0]), "r"((a)[1]), "r"((a)[2]), "r"((a)[3]),                  \
          "r"(b0v), "r"(b1v))

// pack two floats -> bf16x2 word (x = low half), and residuals
__device__ __forceinline__ uint32_t pack_bf16x2(float x, float y) {
    __nv_bfloat162 h = __floats2bfloat162_rn(x, y);
    return *reinterpret_cast<uint32_t*>(&h);
}

// ---------------------------------------------------------------------------
// GEMM1 (mma.sync bf16 m16n8k16, 3x hi/lo split) + fused exp + row-sum:
//   E[b,c,m] = exp(sum_d ctx[b,c,d]*main[b,m,d])
// CTA tile 128x128, BK=32, 256 threads, warp tile 64x32, occ 2.
// smem: 4 tiles [128 rows][k word-stride 20] of bf16x2 words (40960 B).
// 20r + lk4 mod 32 is distinct over the (8 row x 4 kpair) lane footprint ->
// conflict-free fragment LDS.
// ---------------------------------------------------------------------------
#define WS1 20
#define SMEM1_BYTES (4 * 128 * WS1 * 4)   // 40960

__global__ __launch_bounds__(256, 2) void gemm1_mma(const float* __restrict__ ctx,
                                                    const float* __restrict__ mn) {
    extern __shared__ uint32_t sm1[];
    uint32_t* sAH = sm1;
    uint32_t* sAL = sm1 + 128 * WS1;
    uint32_t* sBH = sm1 + 2 * 128 * WS1;
    uint32_t* sBL = sm1 + 3 * 128 * WS1;

    const int b  = blockIdx.z;
    const int c0 = blockIdx.y * 128;
    const int m0 = blockIdx.x * 128;

    const float* A = ctx + (size_t)b * LSEQ * DIM + (size_t)c0 * DIM;
    const float* B = mn  + (size_t)b * LSEQ * DIM + (size_t)m0 * DIM;
    float*       E = g_S + (size_t)b * LSEQ * LSEQ;

    const int tid  = threadIdx.x;
    const int wid  = tid >> 5;
    const int lane = tid & 31;
    const int wm   = (wid >> 2) * 64;
    const int wn   = (wid & 3) * 32;
    const int lr4  = lane >> 2;
    const int lk4  = lane & 3;

    const int r  = tid >> 1;            // load row 0..127
    const int hw = (tid & 1);           // k half (16 floats each)

    float acc[4][4][4];
#pragma unroll
    for (int i = 0; i < 4; i++)
#pragma unroll
        for (int j = 0; j < 4; j++)
#pragma unroll
            for (int q = 0; q < 4; q++) acc[i][j][q] = 0.0f;

#pragma unroll 1
    for (int ch = 0; ch < 4; ch++) {
        const int dk = ch * 32 + hw * 16;
        __syncthreads();
        const int wbase = r * WS1 + hw * 8;
#pragma unroll
        for (int q = 0; q < 4; q++) {
            float4 av = *(const float4*)(A + (size_t)r * DIM + dk + q * 4);
            float4 bv = *(const float4*)(B + (size_t)r * DIM + dk + q * 4);

            uint32_t h01 = pack_bf16x2(av.x, av.y);
            uint32_t h23 = pack_bf16x2(av.z, av.w);
            __nv_bfloat162* hp = (__nv_bfloat162*)&h01;
            __nv_bfloat162* hq = (__nv_bfloat162*)&h23;
            uint32_t l01 = pack_bf16x2(av.x - __bfloat162float(hp->x),
                                       av.y - __bfloat162float(hp->y));
            uint32_t l23 = pack_bf16x2(av.z - __bfloat162float(hq->x),
                                       av.w - __bfloat162float(hq->y));
            sAH[wbase + 2 * q]     = h01;
            sAH[wbase + 2 * q + 1] = h23;
            sAL[wbase + 2 * q]     = l01;
            sAL[wbase + 2 * q + 1] = l23;

            h01 = pack_bf16x2(bv.x, bv.y);
            h23 = pack_bf16x2(bv.z, bv.w);
            hp = (__nv_bfloat162*)&h01;
            hq = (__nv_bfloat162*)&h23;
            l01 = pack_bf16x2(bv.x - __bfloat162float(hp->x),
                              bv.y - __bfloat162float(hp->y));
            l23 = pack_bf16x2(bv.z - __bfloat162float(hq->x),
                              bv.w - __bfloat162float(hq->y));
            sBH[wbase + 2 * q]     = h01;
            sBH[wbase + 2 * q + 1] = h23;
            sBL[wbase + 2 * q]     = l01;
            sBL[wbase + 2 * q + 1] = l23;
        }
        __syncthreads();

#pragma unroll
        for (int ks = 0; ks < 2; ks++) {       // two k16 steps per 32-chunk
            const int k0 = ks * 8;             // word offset within row
            uint32_t ah[4][4], al[4][4];
#pragma unroll
            for (int mt = 0; mt < 4; mt++) {
                const int rr = wm + mt * 16 + lr4;
                const uint32_t* pH = sAH + rr * WS1 + k0 + lk4;
                const uint32_t* pL = sAL + rr * WS1 + k0 + lk4;
                ah[mt][0] = pH[0]; ah[mt][1] = pH[8 * WS1];
                ah[mt][2] = pH[4]; ah[mt][3] = pH[8 * WS1 + 4];
                al[mt][0] = pL[0]; al[mt][1] = pL[8 * WS1];
                al[mt][2] = pL[4]; al[mt][3] = pL[8 * WS1 + 4];
            }
#pragma unroll
            for (int nt = 0; nt < 4; nt++) {
                const int nn = wn + nt * 8 + lr4;
                const uint32_t* qH = sBH + nn * WS1 + k0 + lk4;
                const uint32_t* qL = sBL + nn * WS1 + k0 + lk4;
                const uint32_t bh0 = qH[0], bh1 = qH[4];
                const uint32_t bl0 = qL[0], bl1 = qL[4];
#pragma unroll
                for (int mt = 0; mt < 4; mt++) {
                    MMA_BF16(acc[mt][nt], ah[mt], bh0, bh1);
                    MMA_BF16(acc[mt][nt], ah[mt], bl0, bl1);
                    MMA_BF16(acc[mt][nt], al[mt], bh0, bh1);
                }
            }
        }
    }

    // ---- epilogue: exp, store E, deterministic row partial sums
    __syncthreads();
    float* s_part = (float*)sm1;           // [4 warp-cols][128 rows]

#pragma unroll
    for (int mt = 0; mt < 4; mt++) {
        float s0 = 0.f, s1 = 0.f;
#pragma unroll
        for (int nt = 0; nt < 4; nt++) {
            const float e0 = __expf(acc[mt][nt][0]);
            const float e1 = __expf(acc[mt][nt][1]);
            const float e2 = __expf(acc[mt][nt][2]);
            const float e3 = __expf(acc[mt][nt][3]);
            const int row = c0 + wm + mt * 16 + lr4;
            const int col = m0 + wn + nt * 8 + 2 * lk4;
            *(float2*)&E[(size_t)row * LSEQ + col]       = make_float2(e0, e1);
            *(float2*)&E[(size_t)(row + 8) * LSEQ + col] = make_float2(e2, e3);
            s0 += e0 + e1;
            s1 += e2 + e3;
        }
        s0 += __shfl_xor_sync(0xffffffffu, s0, 1);
        s0 += __shfl_xor_sync(0xffffffffu, s0, 2);
        s1 += __shfl_xor_sync(0xffffffffu, s1, 1);
        s1 += __shfl_xor_sync(0xffffffffu, s1, 2);
        if (lk4 == 0) {
            s_part[(wid & 3) * 128 + wm + mt * 16 + lr4]     = s0;
            s_part[(wid & 3) * 128 + wm + mt * 16 + lr4 + 8] = s1;
        }
    }
    __syncthreads();
    if (tid < 128) {
        const float tot = ((s_part[tid] + s_part[128 + tid]) +
                           (s_part[256 + tid] + s_part[384 + tid]));
        g_esum[((size_t)b * LSEQ + c0 + tid) * 16 + blockIdx.x] = tot;
    }
}

// ---------------------------------------------------------------------------
// inv: g_inv[row] = 1 / sum_{t<16} g_esum[row][t]
// ---------------------------------------------------------------------------
__global__ __launch_bounds__(256) void inv_kernel() {
    const int i = blockIdx.x * 256 + threadIdx.x;
    const float4* p = (const float4*)(g_esum + (size_t)i * 16);
    float4 a = p[0], b4 = p[1], c = p[2], d = p[3];
    const float tot = (((a.x + a.y) + (a.z + a.w)) + ((b4.x + b4.y) + (b4.z + b4.w)))
                    + (((c.x + c.y) + (c.z + c.w)) + ((d.x + d.y) + (d.z + d.w)));
    g_inv[i] = 1.0f / tot;
}

// ---------------------------------------------------------------------------
// GEMM2 (mma.sync tf32, split-K):
//   part[s][b][m][d] = sum_c (E[b,c,m]*inv[b,c]) * ctx[b,c,d]
// ---------------------------------------------------------------------------
#define PAD2 132

__global__ __launch_bounds__(256, 2) void gemm2_mma(const float* __restrict__ ctx) {
    __shared__ uint32_t sP[32 * PAD2];
    __shared__ uint32_t sC[32 * PAD2];

    const int sp = blockIdx.x;
    const int m0 = blockIdx.y * 128;
    const int b  = blockIdx.z;
    const int cbase = sp * KSPLIT;

    const float* Ebuf = g_S + (size_t)b * LSEQ * LSEQ;
    const float* C = ctx + (size_t)b * LSEQ * DIM;
    float* PT = g_part + ((size_t)sp * NB + b) * LSEQ * DIM;

    const int tid  = threadIdx.x;
    const int wid  = tid >> 5;
    const int lane = tid & 31;
    const int wm   = (wid >> 2) * 64;
    const int wn   = (wid & 3) * 32;
    const int lr4  = lane >> 2;
    const int lk4  = lane & 3;

    const int kc = tid >> 3;            // 0..31
    const int mq = (tid & 7) * 16;      // 0..112

    float acc[4][4][4];
#pragma unroll
    for (int i = 0; i < 4; i++)
#pragma unroll
        for (int j = 0; j < 4; j++)
#pragma unroll
            for (int q = 0; q < 4; q++) acc[i][j][q] = 0.0f;

#pragma unroll 1
    for (int ch = 0; ch < KSPLIT / 32; ch++) {
        const int crow = cbase + ch * 32 + kc;
        const float inv = g_inv[(size_t)b * LSEQ + crow];
        __syncthreads();
#pragma unroll
        for (int q = 0; q < 4; q++) {
            float4 pv = *(const float4*)(Ebuf + (size_t)crow * LSEQ + m0 + mq + q * 4);
            float4 cv = *(const float4*)(C + (size_t)crow * DIM + mq + q * 4);
            pv.x *= inv; pv.y *= inv; pv.z *= inv; pv.w *= inv;
            *(uint4*)&sP[kc * PAD2 + mq + q * 4] =
                make_uint4(f2tf32(pv.x), f2tf32(pv.y), f2tf32(pv.z), f2tf32(pv.w));
            *(uint4*)&sC[kc * PAD2 + mq + q * 4] =
                make_uint4(f2tf32(cv.x), f2tf32(cv.y), f2tf32(cv.z), f2tf32(cv.w));
        }
        __syncthreads();

#pragma unroll
        for (int k8 = 0; k8 < 4; k8++) {
            const int k0 = k8 * 8;
            uint32_t a[4][4];
#pragma unroll
            for (int mt = 0; mt < 4; mt++) {
                const int mm = wm + mt * 16 + lr4;
                const uint32_t* p = sP + (k0 + lk4) * PAD2 + mm;
                a[mt][0] = p[0];
                a[mt][1] = p[8];
                a[mt][2] = p[4 * PAD2];
                a[mt][3] = p[4 * PAD2 + 8];
            }
#pragma unroll
            for (int nt = 0; nt < 4; nt++) {
                const int nn = wn + nt * 8 + lr4;
                const uint32_t* q = sC + (k0 + lk4) * PAD2 + nn;
                const uint32_t b0 = q[0], b1 = q[4 * PAD2];
#pragma unroll
                for (int mt = 0; mt < 4; mt++) MMA_TF32(acc[mt][nt], a[mt], b0, b1);
            }
        }
    }

#pragma unroll
    for (int mt = 0; mt < 4; mt++) {
#pragma unroll
        for (int nt = 0; nt < 4; nt++) {
            const int row = m0 + wm + mt * 16 + lr4;
            const int col = wn + nt * 8 + 2 * lk4;
            *(float2*)&PT[(size_t)row * DIM + col] =
                make_float2(acc[mt][nt][0], acc[mt][nt][1]);
            *(float2*)&PT[(size_t)(row + 8) * DIM + col] =
                make_float2(acc[mt][nt][2], acc[mt][nt][3]);
        }
    }
}

// ---------------------------------------------------------------------------
// Reduce: out[b,m,d] = main[b,m,d] - sum_s part[s][b][m][d]
// ---------------------------------------------------------------------------
__global__ __launch_bounds__(256) void reduce_kernel(const float* __restrict__ mn,
                                                     float* __restrict__ out) {
    const size_t i = (size_t)blockIdx.x * blockDim.x + threadIdx.x;
    const size_t stride4 = (size_t)NB * LSEQ * DIM / 4;
    float4 m = ((const float4*)mn)[i];
    float4 s = make_float4(0.f, 0.f, 0.f, 0.f);
    const float4* p4 = (const float4*)g_part;
#pragma unroll
    for (int sp = 0; sp < NSPLIT; sp++) {
        float4 v = p4[(size_t)sp * stride4 + i];
        s.x += v.x; s.y += v.y; s.z += v.z; s.w += v.w;
    }
    ((float4*)out)[i] = make_float4(m.x - s.x, m.y - s.y, m.z - s.z, m.w - s.w);
}

extern "C" void kernel_launch(void* const* d_in, const int* in_sizes, int n_in,
                              void* d_out, int out_size) {
    (void)in_sizes; (void)n_in; (void)out_size;
    const float* ctx = (const float*)d_in[0];  // context: (8, 2048, 128) f32
    const float* mn  = (const float*)d_in[1];  // main:    (8, 2048, 128) f32
    float* out = (float*)d_out;                // (8, 2048, 128) f32

    cudaFuncSetAttribute(gemm1_mma, cudaFuncAttributeMaxDynamicSharedMemorySize, SMEM1_BYTES);

    dim3 g1(LSEQ / 128, LSEQ / 128, NB);       // 16 x 16 x 8
    gemm1_mma<<<g1, 256, SMEM1_BYTES>>>(ctx, mn);

    inv_kernel<<<NB * LSEQ / 256, 256>>>();

    dim3 g2(NSPLIT, LSEQ / 128, NB);           // 8 x 16 x 8
    gemm2_mma<<<g2, 256>>>(ctx);

    const int n4 = NB * LSEQ * DIM / 4;        // 524288 float4
    reduce_kernel<<<n4 / 256, 256>>>(mn, out);
}

// round 8
// speedup vs baseline: 2.1933x; 1.0262x over previous
#include <cuda_runtime.h>
#include <cuda_bf16.h>
#include <cstdint>

#define NB 8
#define LSEQ 2048
#define DIM 128
#define NSPLIT 8
#define KSPLIT (LSEQ / NSPLIT)   // 256

// 128 MiB scratch: E[b,c,m] = exp(S[b,c,m])
static __device__ float g_S[(size_t)NB * LSEQ * LSEQ];
// 64 MiB scratch for split-K partials of GEMM2: [split][b][m][d]
static __device__ float g_part[(size_t)NSPLIT * NB * LSEQ * DIM];
// per-(b,c)-row partial sums of E over each of the 16 m-tiles
static __device__ float g_esum[(size_t)NB * LSEQ * 16];
// per-(b,c)-row 1/sum(E)
static __device__ float g_inv[(size_t)NB * LSEQ];
// pre-converted bf16 hi/lo limb words (2 bf16 per uint32): [row][d/2]
#define NWORDS ((size_t)NB * LSEQ * DIM / 2)
static __device__ uint32_t g_cth[NWORDS];
static __device__ uint32_t g_ctl[NWORDS];
static __device__ uint32_t g_mnh[NWORDS];
static __device__ uint32_t g_mnl[NWORDS];

__device__ __forceinline__ uint32_t f2tf32(float x) {
    uint32_t r;
    asm("cvt.rna.tf32.f32 %0, %1;" : "=r"(r) : "f"(x));
    return r;
}
__device__ __forceinline__ uint32_t pack_bf16x2(float x, float y) {
    __nv_bfloat162 h = __floats2bfloat162_rn(x, y);
    return *reinterpret_cast<uint32_t*>(&h);
}

#define MMA_TF32(d, a, b0v, b1v)                                               \
    asm volatile(                                                              \
        "mma.sync.aligned.m16n8k8.row.col.f32.tf32.tf32.f32 "                  \
        "{%0,%1,%2,%3}, {%4,%5,%6,%7}, {%8,%9}, {%0,%1,%2,%3};"                \
        : "+f"((d)[0]), "+f"((d)[1]), "+f"((d)[2]), "+f"((d)[3])               \
        : "r"((a)[0]), "r"((a)[1]), "r"((a)[2]), "r"((a)[3]),                  \
          "r"(b0v), "r"(b1v))

#define MMA_BF16(d, a, b0v, b1v)                                               \
    asm volatile(                                                              \
        "mma.sync.aligned.m16n8k16.row.col.f32.bf16.bf16.f32 "                 \
        "{%0,%1,%2,%3}, {%4,%5,%6,%7}, {%8,%9}, {%0,%1,%2,%3};"                \
        : "+f"((d)[0]), "+f"((d)[1]), "+f"((d)[2]), "+f"((d)[3])               \
        : "r"((a)[0]), "r"((a)[1]), "r"((a)[2]), "r"((a)[3]),                  \
          "r"(b0v), "r"(b1v))

#define CP16(dst, src)                                                         \
    asm volatile("cp.async.cg.shared.global [%0], [%1], 16;"                   \
                 :: "r"(dst), "l"(src))
#define CP_COMMIT() asm volatile("cp.async.commit_group;")
#define CP_WAIT1() asm volatile("cp.async.wait_group 1;")
#define CP_WAIT0() asm volatile("cp.async.wait_group 0;")

// ---------------------------------------------------------------------------
// precvt: split ctx/main into bf16 hi + lo limb word arrays.
// one float4 (2 output words per limb) per thread per matrix.
// ---------------------------------------------------------------------------
__global__ __launch_bounds__(256) void precvt_kernel(const float* __restrict__ ctx,
                                                     const float* __restrict__ mn) {
    const size_t i = (size_t)blockIdx.x * 256 + threadIdx.x;  // float4 index
    {
        float4 v = ((const float4*)ctx)[i];
        uint32_t h01 = pack_bf16x2(v.x, v.y);
        uint32_t h23 = pack_bf16x2(v.z, v.w);
        __nv_bfloat162 hp = *(__nv_bfloat162*)&h01;
        __nv_bfloat162 hq = *(__nv_bfloat162*)&h23;
        g_cth[2 * i]     = h01;
        g_cth[2 * i + 1] = h23;
        g_ctl[2 * i]     = pack_bf16x2(v.x - __bfloat162float(hp.x),
                                       v.y - __bfloat162float(hp.y));
        g_ctl[2 * i + 1] = pack_bf16x2(v.z - __bfloat162float(hq.x),
                                       v.w - __bfloat162float(hq.y));
    }
    {
        float4 v = ((const float4*)mn)[i];
        uint32_t h01 = pack_bf16x2(v.x, v.y);
        uint32_t h23 = pack_bf16x2(v.z, v.w);
        __nv_bfloat162 hp = *(__nv_bfloat162*)&h01;
        __nv_bfloat162 hq = *(__nv_bfloat162*)&h23;
        g_mnh[2 * i]     = h01;
        g_mnh[2 * i + 1] = h23;
        g_mnl[2 * i]     = pack_bf16x2(v.x - __bfloat162float(hp.x),
                                       v.y - __bfloat162float(hp.y));
        g_mnl[2 * i + 1] = pack_bf16x2(v.z - __bfloat162float(hq.x),
                                       v.w - __bfloat162float(hq.y));
    }
}

// ---------------------------------------------------------------------------
// GEMM1 (mma.sync bf16 m16n8k16, 3x hi/lo split, cp.async 2-stage):
//   E[b,c,m] = exp(sum_d ctx[b,c,d]*main[b,m,d]); also row partial sums.
// CTA tile 128x128, BK=32, 256 threads, warp tile 64x32, occ 2.
// smem: 2 stages x 4 tiles x [128 rows][word-stride 20]  (81920 B).
// ---------------------------------------------------------------------------
#define WS1 20
#define TILE_W (128 * WS1)                   // 2560 words
#define STAGE_W (4 * TILE_W)                 // 10240 words
#define SMEM1_BYTES (2 * STAGE_W * 4)        // 81920

__global__ __launch_bounds__(256, 2) void gemm1_mma() {
    extern __shared__ uint32_t sm1[];
    const int tid  = threadIdx.x;
    const int wid  = tid >> 5;
    const int lane = tid & 31;
    const int wm   = (wid >> 2) * 64;
    const int wn   = (wid & 3) * 32;
    const int lr4  = lane >> 2;
    const int lk4  = lane & 3;

    const int b  = blockIdx.z;
    const int c0 = blockIdx.y * 128;
    const int m0 = blockIdx.x * 128;

    const uint32_t* AH = g_cth + ((size_t)b * LSEQ + c0) * (DIM / 2);
    const uint32_t* AL = g_ctl + ((size_t)b * LSEQ + c0) * (DIM / 2);
    const uint32_t* BH = g_mnh + ((size_t)b * LSEQ + m0) * (DIM / 2);
    const uint32_t* BL = g_mnl + ((size_t)b * LSEQ + m0) * (DIM / 2);
    float* E = g_S + (size_t)b * LSEQ * LSEQ;

    uint32_t sb;
    asm("{ .reg .u64 t; cvta.to.shared.u64 t, %1; cvt.u32.u64 %0, t; }"
        : "=r"(sb) : "l"(sm1));

    const int r  = tid >> 1;            // load row 0..127
    const int hw = (tid & 1);           // k half (8 words each)
    const uint32_t dstw = (uint32_t)(r * WS1 + hw * 8);
    const size_t   srcw = (size_t)r * (DIM / 2) + hw * 8;

    float acc[4][4][4];
#pragma unroll
    for (int i = 0; i < 4; i++)
#pragma unroll
        for (int j = 0; j < 4; j++)
#pragma unroll
            for (int q = 0; q < 4; q++) acc[i][j][q] = 0.0f;

    // issue chunk ch into stage s
    auto issue = [&](int ch, int s) {
        const uint32_t d0 = sb + (uint32_t)(s * STAGE_W + dstw) * 4;
        const size_t   sw = srcw + (size_t)ch * 16;
        CP16(d0 + 0 * TILE_W * 4,      AH + sw);
        CP16(d0 + 0 * TILE_W * 4 + 16, AH + sw + 4);
        CP16(d0 + 1 * TILE_W * 4,      AL + sw);
        CP16(d0 + 1 * TILE_W * 4 + 16, AL + sw + 4);
        CP16(d0 + 2 * TILE_W * 4,      BH + sw);
        CP16(d0 + 2 * TILE_W * 4 + 16, BH + sw + 4);
        CP16(d0 + 3 * TILE_W * 4,      BL + sw);
        CP16(d0 + 3 * TILE_W * 4 + 16, BL + sw + 4);
        CP_COMMIT();
    };

    issue(0, 0);

#pragma unroll 1
    for (int ch = 0; ch < 4; ch++) {
        if (ch < 3) issue(ch + 1, (ch + 1) & 1);
        if (ch < 3) { CP_WAIT1(); } else { CP_WAIT0(); }
        __syncthreads();

        const uint32_t* st = sm1 + (ch & 1) * STAGE_W;
        const uint32_t* sAH = st;
        const uint32_t* sAL = st + TILE_W;
        const uint32_t* sBH = st + 2 * TILE_W;
        const uint32_t* sBL = st + 3 * TILE_W;

#pragma unroll
        for (int ks = 0; ks < 2; ks++) {
            const int k0 = ks * 8;
            uint32_t ah[4][4], al[4][4];
#pragma unroll
            for (int mt = 0; mt < 4; mt++) {
                const int rr = wm + mt * 16 + lr4;
                const uint32_t* pH = sAH + rr * WS1 + k0 + lk4;
                const uint32_t* pL = sAL + rr * WS1 + k0 + lk4;
                ah[mt][0] = pH[0]; ah[mt][1] = pH[8 * WS1];
                ah[mt][2] = pH[4]; ah[mt][3] = pH[8 * WS1 + 4];
                al[mt][0] = pL[0]; al[mt][1] = pL[8 * WS1];
                al[mt][2] = pL[4]; al[mt][3] = pL[8 * WS1 + 4];
            }
#pragma unroll
            for (int nt = 0; nt < 4; nt++) {
                const int nn = wn + nt * 8 + lr4;
                const uint32_t* qH = sBH + nn * WS1 + k0 + lk4;
                const uint32_t* qL = sBL + nn * WS1 + k0 + lk4;
                const uint32_t bh0 = qH[0], bh1 = qH[4];
                const uint32_t bl0 = qL[0], bl1 = qL[4];
#pragma unroll
                for (int mt = 0; mt < 4; mt++) {
                    MMA_BF16(acc[mt][nt], ah[mt], bh0, bh1);
                    MMA_BF16(acc[mt][nt], ah[mt], bl0, bl1);
                    MMA_BF16(acc[mt][nt], al[mt], bh0, bh1);
                }
            }
        }
        __syncthreads();
    }

    // ---- epilogue: exp, store E, deterministic row partial sums
    float* s_part = (float*)sm1;           // [4 warp-cols][128 rows]

#pragma unroll
    for (int mt = 0; mt < 4; mt++) {
        float s0 = 0.f, s1 = 0.f;
#pragma unroll
        for (int nt = 0; nt < 4; nt++) {
            const float e0 = __expf(acc[mt][nt][0]);
            const float e1 = __expf(acc[mt][nt][1]);
            const float e2 = __expf(acc[mt][nt][2]);
            const float e3 = __expf(acc[mt][nt][3]);
            const int row = c0 + wm + mt * 16 + lr4;
            const int col = m0 + wn + nt * 8 + 2 * lk4;
            *(float2*)&E[(size_t)row * LSEQ + col]       = make_float2(e0, e1);
            *(float2*)&E[(size_t)(row + 8) * LSEQ + col] = make_float2(e2, e3);
            s0 += e0 + e1;
            s1 += e2 + e3;
        }
        s0 += __shfl_xor_sync(0xffffffffu, s0, 1);
        s0 += __shfl_xor_sync(0xffffffffu, s0, 2);
        s1 += __shfl_xor_sync(0xffffffffu, s1, 1);
        s1 += __shfl_xor_sync(0xffffffffu, s1, 2);
        if (lk4 == 0) {
            s_part[(wid & 3) * 128 + wm + mt * 16 + lr4]     = s0;
            s_part[(wid & 3) * 128 + wm + mt * 16 + lr4 + 8] = s1;
        }
    }
    __syncthreads();
    if (tid < 128) {
        const float tot = ((s_part[tid] + s_part[128 + tid]) +
                           (s_part[256 + tid] + s_part[384 + tid]));
        g_esum[((size_t)b * LSEQ + c0 + tid) * 16 + blockIdx.x] = tot;
    }
}

// ---------------------------------------------------------------------------
// inv: g_inv[row] = 1 / sum_{t<16} g_esum[row][t]
// ---------------------------------------------------------------------------
__global__ __launch_bounds__(256) void inv_kernel() {
    const int i = blockIdx.x * 256 + threadIdx.x;
    const float4* p = (const float4*)(g_esum + (size_t)i * 16);
    float4 a = p[0], b4 = p[1], c = p[2], d = p[3];
    const float tot = (((a.x + a.y) + (a.z + a.w)) + ((b4.x + b4.y) + (b4.z + b4.w)))
                    + (((c.x + c.y) + (c.z + c.w)) + ((d.x + d.y) + (d.z + d.w)));
    g_inv[i] = 1.0f / tot;
}

// ---------------------------------------------------------------------------
// GEMM2 (mma.sync tf32, split-K):
//   part[s][b][m][d] = sum_c (E[b,c,m]*inv[b,c]) * ctx[b,c,d]
// ---------------------------------------------------------------------------
#define PAD2 132

__global__ __launch_bounds__(256, 2) void gemm2_mma(const float* __restrict__ ctx) {
    __shared__ uint32_t sP[32 * PAD2];
    __shared__ uint32_t sC[32 * PAD2];

    const int sp = blockIdx.x;
    const int m0 = blockIdx.y * 128;
    const int b  = blockIdx.z;
    const int cbase = sp * KSPLIT;

    const float* Ebuf = g_S + (size_t)b * LSEQ * LSEQ;
    const float* C = ctx + (size_t)b * LSEQ * DIM;
    float* PT = g_part + ((size_t)sp * NB + b) * LSEQ * DIM;

    const int tid  = threadIdx.x;
    const int wid  = tid >> 5;
    const int lane = tid & 31;
    const int wm   = (wid >> 2) * 64;
    const int wn   = (wid & 3) * 32;
    const int lr4  = lane >> 2;
    const int lk4  = lane & 3;

    const int kc = tid >> 3;            // 0..31
    const int mq = (tid & 7) * 16;      // 0..112

    float acc[4][4][4];
#pragma unroll
    for (int i = 0; i < 4; i++)
#pragma unroll
        for (int j = 0; j < 4; j++)
#pragma unroll
            for (int q = 0; q < 4; q++) acc[i][j][q] = 0.0f;

#pragma unroll 1
    for (int ch = 0; ch < KSPLIT / 32; ch++) {
        const int crow = cbase + ch * 32 + kc;
        const float inv = g_inv[(size_t)b * LSEQ + crow];
        __syncthreads();
#pragma unroll
        for (int q = 0; q < 4; q++) {
            float4 pv = *(const float4*)(Ebuf + (size_t)crow * LSEQ + m0 + mq + q * 4);
            float4 cv = *(const float4*)(C + (size_t)crow * DIM + mq + q * 4);
            pv.x *= inv; pv.y *= inv; pv.z *= inv; pv.w *= inv;
            *(uint4*)&sP[kc * PAD2 + mq + q * 4] =
                make_uint4(f2tf32(pv.x), f2tf32(pv.y), f2tf32(pv.z), f2tf32(pv.w));
            *(uint4*)&sC[kc * PAD2 + mq + q * 4] =
                make_uint4(f2tf32(cv.x), f2tf32(cv.y), f2tf32(cv.z), f2tf32(cv.w));
        }
        __syncthreads();

#pragma unroll
        for (int k8 = 0; k8 < 4; k8++) {
            const int k0 = k8 * 8;
            uint32_t a[4][4];
#pragma unroll
            for (int mt = 0; mt < 4; mt++) {
                const int mm = wm + mt * 16 + lr4;
                const uint32_t* p = sP + (k0 + lk4) * PAD2 + mm;
                a[mt][0] = p[0];
                a[mt][1] = p[8];
                a[mt][2] = p[4 * PAD2];
                a[mt][3] = p[4 * PAD2 + 8];
            }
#pragma unroll
            for (int nt = 0; nt < 4; nt++) {
                const int nn = wn + nt * 8 + lr4;
                const uint32_t* q = sC + (k0 + lk4) * PAD2 + nn;
                const uint32_t b0 = q[0], b1 = q[4 * PAD2];
#pragma unroll
                for (int mt = 0; mt < 4; mt++) MMA_TF32(acc[mt][nt], a[mt], b0, b1);
            }
        }
    }

#pragma unroll
    for (int mt = 0; mt < 4; mt++) {
#pragma unroll
        for (int nt = 0; nt < 4; nt++) {
            const int row = m0 + wm + mt * 16 + lr4;
            const int col = wn + nt * 8 + 2 * lk4;
            *(float2*)&PT[(size_t)row * DIM + col] =
                make_float2(acc[mt][nt][0], acc[mt][nt][1]);
            *(float2*)&PT[(size_t)(row + 8) * DIM + col] =
                make_float2(acc[mt][nt][2], acc[mt][nt][3]);
        }
    }
}

// ---------------------------------------------------------------------------
// Reduce: out[b,m,d] = main[b,m,d] - sum_s part[s][b][m][d]
// ---------------------------------------------------------------------------
__global__ __launch_bounds__(256) void reduce_kernel(const float* __restrict__ mn,
                                                     float* __restrict__ out) {
    const size_t i = (size_t)blockIdx.x * blockDim.x + threadIdx.x;
    const size_t stride4 = (size_t)NB * LSEQ * DIM / 4;
    float4 m = ((const float4*)mn)[i];
    float4 s = make_float4(0.f, 0.f, 0.f, 0.f);
    const float4* p4 = (const float4*)g_part;
#pragma unroll
    for (int sp = 0; sp < NSPLIT; sp++) {
        float4 v = p4[(size_t)sp * stride4 + i];
        s.x += v.x; s.y += v.y; s.z += v.z; s.w += v.w;
    }
    ((float4*)out)[i] = make_float4(m.x - s.x, m.y - s.y, m.z - s.z, m.w - s.w);
}

extern "C" void kernel_launch(void* const* d_in, const int* in_sizes, int n_in,
                              void* d_out, int out_size) {
    (void)in_sizes; (void)n_in; (void)out_size;
    const float* ctx = (const float*)d_in[0];  // context: (8, 2048, 128) f32
    const float* mn  = (const float*)d_in[1];  // main:    (8, 2048, 128) f32
    float* out = (float*)d_out;                // (8, 2048, 128) f32

    cudaFuncSetAttribute(gemm1_mma, cudaFuncAttributeMaxDynamicSharedMemorySize, SMEM1_BYTES);

    precvt_kernel<<<NB * LSEQ * DIM / 4 / 256, 256>>>(ctx, mn);

    dim3 g1(LSEQ / 128, LSEQ / 128, NB);       // 16 x 16 x 8
    gemm1_mma<<<g1, 256, SMEM1_BYTES>>>();

    inv_kernel<<<NB * LSEQ / 256, 256>>>();

    dim3 g2(NSPLIT, LSEQ / 128, NB);           // 8 x 16 x 8
    gemm2_mma<<<g2, 256>>>(ctx);

    const int n4 = NB * LSEQ * DIM / 4;        // 524288 float4
    reduce_kernel<<<n4 / 256, 256>>>(mn, out);
}

// round 9
// speedup vs baseline: 2.6064x; 1.1883x over previous
#include <cuda_runtime.h>
#include <cuda_bf16.h>
#include <cstdint>

#define NB 8
#define LSEQ 2048
#define DIM 128
#define NSPLIT 8
#define KSPLIT (LSEQ / NSPLIT)   // 256

// 128 MiB scratch: E[b,c,m] = tf32_rounded(exp(S[b,c,m]))
static __device__ float g_S[(size_t)NB * LSEQ * LSEQ];
// 64 MiB scratch for split-K partials of GEMM2: [split][b][m][d]
static __device__ float g_part[(size_t)NSPLIT * NB * LSEQ * DIM];
// per-(b,c)-row partial sums of E over each of the 16 m-tiles
static __device__ float g_esum[(size_t)NB * LSEQ * 16];
// per-(b,c)-row 1/sum(E)
static __device__ float g_inv[(size_t)NB * LSEQ];
// pre-converted bf16 hi/lo limb words (2 bf16 per uint32): [row][d/2]
#define NWORDS ((size_t)NB * LSEQ * DIM / 2)
static __device__ uint32_t g_cth[NWORDS];
static __device__ uint32_t g_ctl[NWORDS];
static __device__ uint32_t g_mnh[NWORDS];
static __device__ uint32_t g_mnl[NWORDS];
// 8 MiB: C'[b,c,d] = tf32_rna(inv[b,c] * ctx[b,c,d])
static __device__ float g_Cs[(size_t)NB * LSEQ * DIM];

__device__ __forceinline__ uint32_t f2tf32(float x) {
    uint32_t r;
    asm("cvt.rna.tf32.f32 %0, %1;" : "=r"(r) : "f"(x));
    return r;
}
__device__ __forceinline__ uint32_t pack_bf16x2(float x, float y) {
    __nv_bfloat162 h = __floats2bfloat162_rn(x, y);
    return *reinterpret_cast<uint32_t*>(&h);
}

#define MMA_TF32(d, a, b0v, b1v)                                               \
    asm volatile(                                                              \
        "mma.sync.aligned.m16n8k8.row.col.f32.tf32.tf32.f32 "                  \
        "{%0,%1,%2,%3}, {%4,%5,%6,%7}, {%8,%9}, {%0,%1,%2,%3};"                \
        : "+f"((d)[0]), "+f"((d)[1]), "+f"((d)[2]), "+f"((d)[3])               \
        : "r"((a)[0]), "r"((a)[1]), "r"((a)[2]), "r"((a)[3]),                  \
          "r"(b0v), "r"(b1v))

#define MMA_BF16(d, a, b0v, b1v)                                               \
    asm volatile(                                                              \
        "mma.sync.aligned.m16n8k16.row.col.f32.bf16.bf16.f32 "                 \
        "{%0,%1,%2,%3}, {%4,%5,%6,%7}, {%8,%9}, {%0,%1,%2,%3};"                \
        : "+f"((d)[0]), "+f"((d)[1]), "+f"((d)[2]), "+f"((d)[3])               \
        : "r"((a)[0]), "r"((a)[1]), "r"((a)[2]), "r"((a)[3]),                  \
          "r"(b0v), "r"(b1v))

#define CP16(dst, src)                                                         \
    asm volatile("cp.async.cg.shared.global [%0], [%1], 16;"                   \
                 :: "r"(dst), "l"(src))
#define CP_COMMIT() asm volatile("cp.async.commit_group;")
#define CP_WAIT1() asm volatile("cp.async.wait_group 1;")
#define CP_WAIT0() asm volatile("cp.async.wait_group 0;")

// ---------------------------------------------------------------------------
// precvt: split ctx/main into bf16 hi + lo limb word arrays.
// ---------------------------------------------------------------------------
__global__ __launch_bounds__(256) void precvt_kernel(const float* __restrict__ ctx,
                                                     const float* __restrict__ mn) {
    const size_t i = (size_t)blockIdx.x * 256 + threadIdx.x;  // float4 index
    {
        float4 v = ((const float4*)ctx)[i];
        uint32_t h01 = pack_bf16x2(v.x, v.y);
        uint32_t h23 = pack_bf16x2(v.z, v.w);
        __nv_bfloat162 hp = *(__nv_bfloat162*)&h01;
        __nv_bfloat162 hq = *(__nv_bfloat162*)&h23;
        g_cth[2 * i]     = h01;
        g_cth[2 * i + 1] = h23;
        g_ctl[2 * i]     = pack_bf16x2(v.x - __bfloat162float(hp.x),
                                       v.y - __bfloat162float(hp.y));
        g_ctl[2 * i + 1] = pack_bf16x2(v.z - __bfloat162float(hq.x),
                                       v.w - __bfloat162float(hq.y));
    }
    {
        float4 v = ((const float4*)mn)[i];
        uint32_t h01 = pack_bf16x2(v.x, v.y);
        uint32_t h23 = pack_bf16x2(v.z, v.w);
        __nv_bfloat162 hp = *(__nv_bfloat162*)&h01;
        __nv_bfloat162 hq = *(__nv_bfloat162*)&h23;
        g_mnh[2 * i]     = h01;
        g_mnh[2 * i + 1] = h23;
        g_mnl[2 * i]     = pack_bf16x2(v.x - __bfloat162float(hp.x),
                                       v.y - __bfloat162float(hp.y));
        g_mnl[2 * i + 1] = pack_bf16x2(v.z - __bfloat162float(hq.x),
                                       v.w - __bfloat162float(hq.y));
    }
}

// ---------------------------------------------------------------------------
// GEMM1 (bf16 m16n8k16 3x split, cp.async 2-stage) + fused exp + row sums.
// E stored pre-rounded to tf32 so gemm2 can feed raw words to mma.tf32.
// ---------------------------------------------------------------------------
#define WS1 20
#define TILE_W (128 * WS1)
#define STAGE_W (4 * TILE_W)
#define SMEM1_BYTES (2 * STAGE_W * 4)        // 81920

__global__ __launch_bounds__(256, 2) void gemm1_mma() {
    extern __shared__ uint32_t sm1[];
    const int tid  = threadIdx.x;
    const int wid  = tid >> 5;
    const int lane = tid & 31;
    const int wm   = (wid >> 2) * 64;
    const int wn   = (wid & 3) * 32;
    const int lr4  = lane >> 2;
    const int lk4  = lane & 3;

    const int b  = blockIdx.z;
    const int c0 = blockIdx.y * 128;
    const int m0 = blockIdx.x * 128;

    const uint32_t* AH = g_cth + ((size_t)b * LSEQ + c0) * (DIM / 2);
    const uint32_t* AL = g_ctl + ((size_t)b * LSEQ + c0) * (DIM / 2);
    const uint32_t* BH = g_mnh + ((size_t)b * LSEQ + m0) * (DIM / 2);
    const uint32_t* BL = g_mnl + ((size_t)b * LSEQ + m0) * (DIM / 2);
    float* E = g_S + (size_t)b * LSEQ * LSEQ;

    uint32_t sb;
    asm("{ .reg .u64 t; cvta.to.shared.u64 t, %1; cvt.u32.u64 %0, t; }"
        : "=r"(sb) : "l"(sm1));

    const int r  = tid >> 1;
    const int hw = (tid & 1);
    const uint32_t dstw = (uint32_t)(r * WS1 + hw * 8);
    const size_t   srcw = (size_t)r * (DIM / 2) + hw * 8;

    float acc[4][4][4];
#pragma unroll
    for (int i = 0; i < 4; i++)
#pragma unroll
        for (int j = 0; j < 4; j++)
#pragma unroll
            for (int q = 0; q < 4; q++) acc[i][j][q] = 0.0f;

    auto issue = [&](int ch, int s) {
        const uint32_t d0 = sb + (uint32_t)(s * STAGE_W + dstw) * 4;
        const size_t   sw = srcw + (size_t)ch * 16;
        CP16(d0 + 0 * TILE_W * 4,      AH + sw);
        CP16(d0 + 0 * TILE_W * 4 + 16, AH + sw + 4);
        CP16(d0 + 1 * TILE_W * 4,      AL + sw);
        CP16(d0 + 1 * TILE_W * 4 + 16, AL + sw + 4);
        CP16(d0 + 2 * TILE_W * 4,      BH + sw);
        CP16(d0 + 2 * TILE_W * 4 + 16, BH + sw + 4);
        CP16(d0 + 3 * TILE_W * 4,      BL + sw);
        CP16(d0 + 3 * TILE_W * 4 + 16, BL + sw + 4);
        CP_COMMIT();
    };

    issue(0, 0);

#pragma unroll 1
    for (int ch = 0; ch < 4; ch++) {
        if (ch < 3) issue(ch + 1, (ch + 1) & 1);
        if (ch < 3) { CP_WAIT1(); } else { CP_WAIT0(); }
        __syncthreads();

        const uint32_t* st = sm1 + (ch & 1) * STAGE_W;
        const uint32_t* sAH = st;
        const uint32_t* sAL = st + TILE_W;
        const uint32_t* sBH = st + 2 * TILE_W;
        const uint32_t* sBL = st + 3 * TILE_W;

#pragma unroll
        for (int ks = 0; ks < 2; ks++) {
            const int k0 = ks * 8;
            uint32_t ah[4][4], al[4][4];
#pragma unroll
            for (int mt = 0; mt < 4; mt++) {
                const int rr = wm + mt * 16 + lr4;
                const uint32_t* pH = sAH + rr * WS1 + k0 + lk4;
                const uint32_t* pL = sAL + rr * WS1 + k0 + lk4;
                ah[mt][0] = pH[0]; ah[mt][1] = pH[8 * WS1];
                ah[mt][2] = pH[4]; ah[mt][3] = pH[8 * WS1 + 4];
                al[mt][0] = pL[0]; al[mt][1] = pL[8 * WS1];
                al[mt][2] = pL[4]; al[mt][3] = pL[8 * WS1 + 4];
            }
#pragma unroll
            for (int nt = 0; nt < 4; nt++) {
                const int nn = wn + nt * 8 + lr4;
                const uint32_t* qH = sBH + nn * WS1 + k0 + lk4;
                const uint32_t* qL = sBL + nn * WS1 + k0 + lk4;
                const uint32_t bh0 = qH[0], bh1 = qH[4];
                const uint32_t bl0 = qL[0], bl1 = qL[4];
#pragma unroll
                for (int mt = 0; mt < 4; mt++) {
                    MMA_BF16(acc[mt][nt], ah[mt], bh0, bh1);
                    MMA_BF16(acc[mt][nt], ah[mt], bl0, bl1);
                    MMA_BF16(acc[mt][nt], al[mt], bh0, bh1);
                }
            }
        }
        __syncthreads();
    }

    // epilogue: exp -> round to tf32 -> store; deterministic row partial sums
    float* s_part = (float*)sm1;

#pragma unroll
    for (int mt = 0; mt < 4; mt++) {
        float s0 = 0.f, s1 = 0.f;
#pragma unroll
        for (int nt = 0; nt < 4; nt++) {
            const float e0 = __uint_as_float(f2tf32(__expf(acc[mt][nt][0])));
            const float e1 = __uint_as_float(f2tf32(__expf(acc[mt][nt][1])));
            const float e2 = __uint_as_float(f2tf32(__expf(acc[mt][nt][2])));
            const float e3 = __uint_as_float(f2tf32(__expf(acc[mt][nt][3])));
            const int row = c0 + wm + mt * 16 + lr4;
            const int col = m0 + wn + nt * 8 + 2 * lk4;
            *(float2*)&E[(size_t)row * LSEQ + col]       = make_float2(e0, e1);
            *(float2*)&E[(size_t)(row + 8) * LSEQ + col] = make_float2(e2, e3);
            s0 += e0 + e1;
            s1 += e2 + e3;
        }
        s0 += __shfl_xor_sync(0xffffffffu, s0, 1);
        s0 += __shfl_xor_sync(0xffffffffu, s0, 2);
        s1 += __shfl_xor_sync(0xffffffffu, s1, 1);
        s1 += __shfl_xor_sync(0xffffffffu, s1, 2);
        if (lk4 == 0) {
            s_part[(wid & 3) * 128 + wm + mt * 16 + lr4]     = s0;
            s_part[(wid & 3) * 128 + wm + mt * 16 + lr4 + 8] = s1;
        }
    }
    __syncthreads();
    if (tid < 128) {
        const float tot = ((s_part[tid] + s_part[128 + tid]) +
                           (s_part[256 + tid] + s_part[384 + tid]));
        g_esum[((size_t)b * LSEQ + c0 + tid) * 16 + blockIdx.x] = tot;
    }
}

// ---------------------------------------------------------------------------
// inv: g_inv[row] = 1 / sum_{t<16} g_esum[row][t]
// ---------------------------------------------------------------------------
__global__ __launch_bounds__(256) void inv_kernel() {
    const int i = blockIdx.x * 256 + threadIdx.x;
    const float4* p = (const float4*)(g_esum + (size_t)i * 16);
    float4 a = p[0], b4 = p[1], c = p[2], d = p[3];
    const float tot = (((a.x + a.y) + (a.z + a.w)) + ((b4.x + b4.y) + (b4.z + b4.w)))
                    + (((c.x + c.y) + (c.z + c.w)) + ((d.x + d.y) + (d.z + d.w)));
    g_inv[i] = 1.0f / tot;
}

// ---------------------------------------------------------------------------
// scale_ctx: g_Cs[b,c,d] = tf32_rna(inv[b,c] * ctx[b,c,d])
// ---------------------------------------------------------------------------
__global__ __launch_bounds__(256) void scale_ctx_kernel(const float* __restrict__ ctx) {
    const size_t i = (size_t)blockIdx.x * 256 + threadIdx.x;  // float4 index
    const float inv = g_inv[i >> 5];                          // 32 float4 per row
    float4 v = ((const float4*)ctx)[i];
    uint4 o = make_uint4(f2tf32(v.x * inv), f2tf32(v.y * inv),
                         f2tf32(v.z * inv), f2tf32(v.w * inv));
    ((uint4*)g_Cs)[i] = o;
}

// ---------------------------------------------------------------------------
// GEMM2 (tf32, split-K, cp.async 2-stage, zero consumer ALU):
//   part[s][b][m][d] = sum_c E[b,c,m] * Cs[b,c,d]      (both pre-tf32-rounded)
// smem: 2 stages x (E tile [32][128] + C tile [32][128]) word-stride 136.
// ---------------------------------------------------------------------------
#define WS2 136
#define T2_W (32 * WS2)                      // 4352 words per tile
#define STG2_W (2 * T2_W)                    // 8704 words per stage
#define SMEM2_BYTES (2 * STG2_W * 4)         // 69632

__global__ __launch_bounds__(256, 2) void gemm2_mma() {
    extern __shared__ uint32_t sm2[];
    const int sp = blockIdx.x;
    const int m0 = blockIdx.y * 128;
    const int b  = blockIdx.z;
    const int cbase = sp * KSPLIT;

    const float* Ebuf = g_S  + (size_t)b * LSEQ * LSEQ;
    const float* Cbuf = g_Cs + (size_t)b * LSEQ * DIM;
    float* PT = g_part + ((size_t)sp * NB + b) * LSEQ * DIM;

    const int tid  = threadIdx.x;
    const int wid  = tid >> 5;
    const int lane = tid & 31;
    const int wm   = (wid >> 2) * 64;
    const int wn   = (wid & 3) * 32;
    const int lr4  = lane >> 2;
    const int lk4  = lane & 3;

    const int kc = tid >> 3;            // 0..31 (c within chunk)
    const int mq = (tid & 7) * 16;      // 0..112 (column start)

    uint32_t sb;
    asm("{ .reg .u64 t; cvta.to.shared.u64 t, %1; cvt.u32.u64 %0, t; }"
        : "=r"(sb) : "l"(sm2));
    const uint32_t dstw = (uint32_t)(kc * WS2 + mq);

    float acc[4][4][4];
#pragma unroll
    for (int i = 0; i < 4; i++)
#pragma unroll
        for (int j = 0; j < 4; j++)
#pragma unroll
            for (int q = 0; q < 4; q++) acc[i][j][q] = 0.0f;

    auto issue = [&](int ch, int s) {
        const int crow = cbase + ch * 32 + kc;
        const float* esrc = Ebuf + (size_t)crow * LSEQ + m0 + mq;
        const float* csrc = Cbuf + (size_t)crow * DIM + mq;
        const uint32_t d0 = sb + (uint32_t)(s * STG2_W + dstw) * 4;
        CP16(d0,                    esrc);
        CP16(d0 + 16,               esrc + 4);
        CP16(d0 + 32,               esrc + 8);
        CP16(d0 + 48,               esrc + 12);
        CP16(d0 + T2_W * 4,         csrc);
        CP16(d0 + T2_W * 4 + 16,    csrc + 4);
        CP16(d0 + T2_W * 4 + 32,    csrc + 8);
        CP16(d0 + T2_W * 4 + 48,    csrc + 12);
        CP_COMMIT();
    };

    issue(0, 0);

#pragma unroll 1
    for (int ch = 0; ch < KSPLIT / 32; ch++) {
        if (ch < KSPLIT / 32 - 1) issue(ch + 1, (ch + 1) & 1);
        if (ch < KSPLIT / 32 - 1) { CP_WAIT1(); } else { CP_WAIT0(); }
        __syncthreads();

        const uint32_t* st = sm2 + (ch & 1) * STG2_W;
        const uint32_t* sE = st;
        const uint32_t* sC = st + T2_W;

#pragma unroll
        for (int k8 = 0; k8 < 4; k8++) {
            const int k0 = k8 * 8;
            uint32_t a[4][4];
#pragma unroll
            for (int mt = 0; mt < 4; mt++) {
                const int mm = wm + mt * 16 + lr4;
                const uint32_t* p = sE + (k0 + lk4) * WS2 + mm;
                a[mt][0] = p[0];
                a[mt][1] = p[8];
                a[mt][2] = p[4 * WS2];
                a[mt][3] = p[4 * WS2 + 8];
            }
#pragma unroll
            for (int nt = 0; nt < 4; nt++) {
                const int nn = wn + nt * 8 + lr4;
                const uint32_t* q = sC + (k0 + lk4) * WS2 + nn;
                const uint32_t b0 = q[0], b1 = q[4 * WS2];
#pragma unroll
                for (int mt = 0; mt < 4; mt++) MMA_TF32(acc[mt][nt], a[mt], b0, b1);
            }
        }
        __syncthreads();
    }

#pragma unroll
    for (int mt = 0; mt < 4; mt++) {
#pragma unroll
        for (int nt = 0; nt < 4; nt++) {
            const int row = m0 + wm + mt * 16 + lr4;
            const int col = wn + nt * 8 + 2 * lk4;
            *(float2*)&PT[(size_t)row * DIM + col] =
                make_float2(acc[mt][nt][0], acc[mt][nt][1]);
            *(float2*)&PT[(size_t)(row + 8) * DIM + col] =
                make_float2(acc[mt][nt][2], acc[mt][nt][3]);
        }
    }
}

// ---------------------------------------------------------------------------
// Reduce: out[b,m,d] = main[b,m,d] - sum_s part[s][b][m][d]
// ---------------------------------------------------------------------------
__global__ __launch_bounds__(256) void reduce_kernel(const float* __restrict__ mn,
                                                     float* __restrict__ out) {
    const size_t i = (size_t)blockIdx.x * blockDim.x + threadIdx.x;
    const size_t stride4 = (size_t)NB * LSEQ * DIM / 4;
    float4 m = ((const float4*)mn)[i];
    float4 s = make_float4(0.f, 0.f, 0.f, 0.f);
    const float4* p4 = (const float4*)g_part;
#pragma unroll
    for (int sp = 0; sp < NSPLIT; sp++) {
        float4 v = p4[(size_t)sp * stride4 + i];
        s.x += v.x; s.y += v.y; s.z += v.z; s.w += v.w;
    }
    ((float4*)out)[i] = make_float4(m.x - s.x, m.y - s.y, m.z - s.z, m.w - s.w);
}

extern "C" void kernel_launch(void* const* d_in, const int* in_sizes, int n_in,
                              void* d_out, int out_size) {
    (void)in_sizes; (void)n_in; (void)out_size;
    const float* ctx = (const float*)d_in[0];  // context: (8, 2048, 128) f32
    const float* mn  = (const float*)d_in[1];  // main:    (8, 2048, 128) f32
    float* out = (float*)d_out;                // (8, 2048, 128) f32

    cudaFuncSetAttribute(gemm1_mma, cudaFuncAttributeMaxDynamicSharedMemorySize, SMEM1_BYTES);
    cudaFuncSetAttribute(gemm2_mma, cudaFuncAttributeMaxDynamicSharedMemorySize, SMEM2_BYTES);

    precvt_kernel<<<NB * LSEQ * DIM / 4 / 256, 256>>>(ctx, mn);

    dim3 g1(LSEQ / 128, LSEQ / 128, NB);       // 16 x 16 x 8
    gemm1_mma<<<g1, 256, SMEM1_BYTES>>>();

    inv_kernel<<<NB * LSEQ / 256, 256>>>();

    scale_ctx_kernel<<<NB * LSEQ * DIM / 4 / 256, 256>>>(ctx);

    dim3 g2(NSPLIT, LSEQ / 128, NB);           // 8 x 16 x 8
    gemm2_mma<<<g2, 256, SMEM2_BYTES>>>();

    const int n4 = NB * LSEQ * DIM / 4;        // 524288 float4
    reduce_kernel<<<n4 / 256, 256>>>(mn, out);
}